// round 1
// baseline (speedup 1.0000x reference)
#include <cuda_runtime.h>
#include <cstddef>

#define BB  16
#define LL  1536
#define DD  512
#define DFF 2048
#define BLD (BB*LL*DD)

// ---------------- device scratch (static globals; no allocation allowed) ----------------
__device__ float g_Q[BLD];
__device__ float g_K[BLD];
__device__ float g_V[BLD];
__device__ float g_O[BLD];
__device__ float g_S[BLD];
__device__ float g_T[BLD];
__device__ float g_W1[BLD];
__device__ float g_H[(size_t)BB*LL*DFF];
__device__ float g_R[BB*LL];
__device__ float g_SW[BB*8];
__device__ int   g_IDX[8];

// ---------------- generic fp32 GEMM: C = A @ B^T (+bias)(+resid)(relu)(accum) ----------
// A: [M,K] row-major (rows optionally circularly shifted by `shift` within each batch of 1536)
// B element (n,k) at Bw[n*ldn + k*ldk]
// 128x128 block, BK=8, 256 threads, 8x8 microtile (split 4+4 at distance 64)
__global__ __launch_bounds__(256, 2)
void gemm_kernel(const float* __restrict__ A, const float* __restrict__ Bw,
                 float* __restrict__ C,
                 const float* __restrict__ bias, const float* __restrict__ resid,
                 int M, int N, int K, int ldn, int ldk,
                 int shift, int relu, int accum)
{
    __shared__ float As[8][128];
    __shared__ float Bs[8][128];
    const int tid = threadIdx.x;
    const int tx = tid & 15, ty = tid >> 4;
    const int m0 = blockIdx.y * 128, n0 = blockIdx.x * 128;

    // A loader: one float4 per thread
    const int arl = tid >> 1, ak0 = (tid & 1) * 4;
    int grow = m0 + arl;
    if (shift != 0) {
        int b = grow / LL, l = grow % LL;
        l += shift;
        if (l < 0) l += LL; else if (l >= LL) l -= LL;
        grow = b * LL + l;
    }
    const float* Ap = A + (size_t)grow * K + ak0;
    // B loader
    const int nrl = tid >> 1, bk0 = (tid & 1) * 4;

    float acc[8][8];
#pragma unroll
    for (int i = 0; i < 8; i++)
#pragma unroll
        for (int j = 0; j < 8; j++) acc[i][j] = 0.f;

    for (int k0 = 0; k0 < K; k0 += 8) {
        float4 av = *reinterpret_cast<const float4*>(Ap + k0);
        As[ak0+0][arl] = av.x; As[ak0+1][arl] = av.y;
        As[ak0+2][arl] = av.z; As[ak0+3][arl] = av.w;
        if (ldk == 1) {
            float4 bv = *reinterpret_cast<const float4*>(Bw + (size_t)(n0+nrl)*ldn + (k0 + bk0));
            Bs[bk0+0][nrl] = bv.x; Bs[bk0+1][nrl] = bv.y;
            Bs[bk0+2][nrl] = bv.z; Bs[bk0+3][nrl] = bv.w;
        } else {
            const float* bp = Bw + (size_t)(n0+nrl)*ldn + (size_t)(k0 + bk0)*ldk;
            Bs[bk0+0][nrl] = bp[0];
            Bs[bk0+1][nrl] = bp[ldk];
            Bs[bk0+2][nrl] = bp[2*ldk];
            Bs[bk0+3][nrl] = bp[3*ldk];
        }
        __syncthreads();
#pragma unroll
        for (int kk = 0; kk < 8; kk++) {
            float4 a0 = *reinterpret_cast<const float4*>(&As[kk][ty*4]);
            float4 a1 = *reinterpret_cast<const float4*>(&As[kk][64 + ty*4]);
            float4 b0 = *reinterpret_cast<const float4*>(&Bs[kk][tx*4]);
            float4 b1 = *reinterpret_cast<const float4*>(&Bs[kk][64 + tx*4]);
            float aa[8] = {a0.x,a0.y,a0.z,a0.w,a1.x,a1.y,a1.z,a1.w};
            float bb[8] = {b0.x,b0.y,b0.z,b0.w,b1.x,b1.y,b1.z,b1.w};
#pragma unroll
            for (int i = 0; i < 8; i++)
#pragma unroll
                for (int j = 0; j < 8; j++)
                    acc[i][j] += aa[i] * bb[j];
        }
        __syncthreads();
    }

    // epilogue
#pragma unroll
    for (int i = 0; i < 8; i++) {
        int m = m0 + ((i < 4) ? (ty*4 + i) : (64 + ty*4 + (i-4)));
#pragma unroll
        for (int jh = 0; jh < 2; jh++) {
            int n = n0 + jh*64 + tx*4;
            float4 v;
            v.x = acc[i][jh*4+0]; v.y = acc[i][jh*4+1];
            v.z = acc[i][jh*4+2]; v.w = acc[i][jh*4+3];
            if (bias) {
                v.x += bias[n+0]; v.y += bias[n+1];
                v.z += bias[n+2]; v.w += bias[n+3];
            }
            if (resid) {
                float4 rv = *reinterpret_cast<const float4*>(&resid[(size_t)m*N + n]);
                v.x += rv.x; v.y += rv.y; v.z += rv.z; v.w += rv.w;
            }
            if (relu) {
                v.x = fmaxf(v.x, 0.f); v.y = fmaxf(v.y, 0.f);
                v.z = fmaxf(v.z, 0.f); v.w = fmaxf(v.w, 0.f);
            }
            float* cp = &C[(size_t)m*N + n];
            if (accum) {
                float4 o = *reinterpret_cast<const float4*>(cp);
                v.x += o.x; v.y += o.y; v.z += o.z; v.w += o.w;
            }
            *reinterpret_cast<float4*>(cp) = v;
        }
    }
}

// ---------------- circular correlation via diag-summed GEMM ------------------------------
// r[b,tau] += sum over tile of Q[b,i,:].K[b,j,:] where tau = (i-j) mod L
__global__ __launch_bounds__(256)
void corr_kernel(const float* __restrict__ Q, const float* __restrict__ Kb,
                 float* __restrict__ r)
{
    __shared__ float Qs[16][64];
    __shared__ float Ks[16][64];
    __shared__ float diag[127];
    const int b  = blockIdx.z;
    const int i0 = blockIdx.y * 64, j0 = blockIdx.x * 64;
    const float* Qb = Q + (size_t)b * LL * DD;
    const float* KB = Kb + (size_t)b * LL * DD;
    const int tid = threadIdx.x;
    const int tx = tid & 15, ty = tid >> 4;
    const int rl = tid >> 2, kl = (tid & 3) * 4;

    float acc[4][4];
#pragma unroll
    for (int i = 0; i < 4; i++)
#pragma unroll
        for (int j = 0; j < 4; j++) acc[i][j] = 0.f;

    for (int k0 = 0; k0 < DD; k0 += 16) {
        float4 qv = *reinterpret_cast<const float4*>(&Qb[(size_t)(i0+rl)*DD + k0 + kl]);
        Qs[kl+0][rl] = qv.x; Qs[kl+1][rl] = qv.y; Qs[kl+2][rl] = qv.z; Qs[kl+3][rl] = qv.w;
        float4 kv = *reinterpret_cast<const float4*>(&KB[(size_t)(j0+rl)*DD + k0 + kl]);
        Ks[kl+0][rl] = kv.x; Ks[kl+1][rl] = kv.y; Ks[kl+2][rl] = kv.z; Ks[kl+3][rl] = kv.w;
        __syncthreads();
#pragma unroll
        for (int kk = 0; kk < 16; kk++) {
            float4 a4 = *reinterpret_cast<const float4*>(&Qs[kk][ty*4]);
            float4 b4 = *reinterpret_cast<const float4*>(&Ks[kk][tx*4]);
            float aa[4] = {a4.x,a4.y,a4.z,a4.w};
            float bb[4] = {b4.x,b4.y,b4.z,b4.w};
#pragma unroll
            for (int i = 0; i < 4; i++)
#pragma unroll
                for (int j = 0; j < 4; j++)
                    acc[i][j] += aa[i] * bb[j];
        }
        __syncthreads();
    }

    if (tid < 127) diag[tid] = 0.f;
    __syncthreads();

    float d7[7] = {0,0,0,0,0,0,0};
#pragma unroll
    for (int i = 0; i < 4; i++)
#pragma unroll
        for (int j = 0; j < 4; j++)
            d7[i - j + 3] += acc[i][j];
    const int base = 60 + 4 * (ty - tx);   // index = 63 + 4*(ty-tx) + (c-3)
#pragma unroll
    for (int c = 0; c < 7; c++)
        atomicAdd(&diag[base + c], d7[c]);
    __syncthreads();

    if (tid < 127) {
        int tau = (i0 - j0 + tid - 63) % LL;
        if (tau < 0) tau += LL;
        atomicAdd(&r[(size_t)b * LL + tau], diag[tid]);
    }
}

// ---------------- zero helper ------------------------------------------------------------
__global__ void zero_kernel(float* p, int n)
{
    int i = blockIdx.x * 256 + threadIdx.x;
    if (i < n) p[i] = 0.f;
}

// ---------------- top-k (k=7) of batch-mean corr + per-batch softmax weights -------------
__global__ void topk_kernel(const float* __restrict__ r, int* __restrict__ gidx,
                            float* __restrict__ gsw)
{
    __shared__ float gv[LL];
    __shared__ float rv[256];
    __shared__ int   ri[256];
    __shared__ int   sidx[7];
    const int tid = threadIdx.x;

    for (int t = tid; t < LL; t += 256) {
        float s = 0.f;
        for (int b = 0; b < BB; b++) s += r[(size_t)b*LL + t];
        gv[t] = s;
    }
    __syncthreads();

    for (int it = 0; it < 7; it++) {
        float bv = -3.4e38f; int bi = 0;
        for (int t = tid; t < LL; t += 256) {
            float v = gv[t];
            if (v > bv) { bv = v; bi = t; }
        }
        rv[tid] = bv; ri[tid] = bi;
        __syncthreads();
        for (int s = 128; s > 0; s >>= 1) {
            if (tid < s) {
                if (rv[tid+s] > rv[tid] ||
                    (rv[tid+s] == rv[tid] && ri[tid+s] < ri[tid])) {
                    rv[tid] = rv[tid+s]; ri[tid] = ri[tid+s];
                }
            }
            __syncthreads();
        }
        if (tid == 0) { sidx[it] = ri[0]; gv[ri[0]] = -3.4e38f; }
        __syncthreads();
    }

    if (tid < 7) gidx[tid] = sidx[tid];
    if (tid < BB) {
        float w[7], m = -3.4e38f;
        for (int i = 0; i < 7; i++) {
            w[i] = r[(size_t)tid*LL + sidx[i]] * (1.0f / (float)DD);
            m = fmaxf(m, w[i]);
        }
        float sum = 0.f;
        for (int i = 0; i < 7; i++) { w[i] = expf(w[i] - m); sum += w[i]; }
        float inv = 1.0f / sum;
        for (int i = 0; i < 7; i++) gsw[tid*7 + i] = w[i] * inv;
    }
}

// ---------------- time-delay aggregation: O[b,l,:] = sum_i w[b,i] * V[b,(l+idx[i])%L,:] ---
__global__ __launch_bounds__(256)
void agg_kernel(const float* __restrict__ V, float* __restrict__ O,
                const int* __restrict__ idxp, const float* __restrict__ swp)
{
    int g = blockIdx.x * 256 + threadIdx.x;     // over BLD/4
    int d4 = g & 127;
    int l  = (g >> 7) % LL;
    int b  = g / (LL * 128);

    int   idx[7];
    float w[7];
#pragma unroll
    for (int i = 0; i < 7; i++) { idx[i] = idxp[i]; w[i] = swp[b*7 + i]; }

    const float4* Vb = reinterpret_cast<const float4*>(V + (size_t)b * LL * DD);
    float4 acc = {0.f, 0.f, 0.f, 0.f};
#pragma unroll
    for (int i = 0; i < 7; i++) {
        int ls = l + idx[i];
        if (ls >= LL) ls -= LL;
        float4 v = Vb[(size_t)ls * 128 + d4];
        acc.x += w[i] * v.x; acc.y += w[i] * v.y;
        acc.z += w[i] * v.z; acc.w += w[i] * v.w;
    }
    reinterpret_cast<float4*>(O)[g] = acc;
}

// ---------------- series_decomp: out = x - movavg_k25(x) (replicate pad) ------------------
__global__ __launch_bounds__(128)
void movavg_kernel(const float* __restrict__ X, float* __restrict__ out)
{
    const int b  = blockIdx.y;
    const int l0 = blockIdx.x * 96;
    const int d4 = threadIdx.x;
    const float4* x = reinterpret_cast<const float4*>(X + (size_t)b * LL * DD) + d4;
    float4* o = reinterpret_cast<float4*>(out + (size_t)b * LL * DD) + d4;

    float4 s = {0.f, 0.f, 0.f, 0.f};
    for (int j = -12; j <= 12; j++) {
        int lc = l0 + j;
        if (lc < 0) lc = 0;
        if (lc > LL-1) lc = LL-1;
        float4 v = x[(size_t)lc * 128];
        s.x += v.x; s.y += v.y; s.z += v.z; s.w += v.w;
    }
    const float inv = 1.0f / 25.0f;
    for (int t = 0; t < 96; t++) {
        int l = l0 + t;
        float4 xc = x[(size_t)l * 128];
        float4 r;
        r.x = xc.x - s.x * inv; r.y = xc.y - s.y * inv;
        r.z = xc.z - s.z * inv; r.w = xc.w - s.w * inv;
        o[(size_t)l * 128] = r;
        int la = l + 13; if (la > LL-1) la = LL-1;
        int lr = l - 12; if (lr < 0)    lr = 0;
        float4 va = x[(size_t)la * 128];
        float4 vr = x[(size_t)lr * 128];
        s.x += va.x - vr.x; s.y += va.y - vr.y;
        s.z += va.z - vr.z; s.w += va.w - vr.w;
    }
}

// ---------------- host-side orchestration ------------------------------------------------
static void run_gemm(const float* A, const float* Bw, float* C,
                     const float* bias, const float* resid,
                     int M, int N, int K, int ldn, int ldk,
                     int shift, int relu, int accum)
{
    dim3 grid(N / 128, M / 128);
    gemm_kernel<<<grid, 256>>>(A, Bw, C, bias, resid, M, N, K, ldn, ldk, shift, relu, accum);
}

static void run_attn(const float* qsrc, const float* kvsrc,
                     const float* W, const float* bias,
                     const float* sprev, float* sdst,
                     float* Q, float* K, float* V, float* O,
                     float* R, int* IDX, float* SW)
{
    const int M = BB * LL;
    run_gemm(qsrc,  W + 0*DD*DD, Q, bias + 0*DD, nullptr, M, DD, DD, DD, 1, 0, 0, 0);
    run_gemm(kvsrc, W + 1*DD*DD, K, bias + 1*DD, nullptr, M, DD, DD, DD, 1, 0, 0, 0);
    run_gemm(kvsrc, W + 2*DD*DD, V, bias + 2*DD, nullptr, M, DD, DD, DD, 1, 0, 0, 0);
    zero_kernel<<<(BB*LL + 255)/256, 256>>>(R, BB*LL);
    dim3 cg(LL/64, LL/64, BB);
    corr_kernel<<<cg, 256>>>(Q, K, R);
    topk_kernel<<<1, 256>>>(R, IDX, SW);
    agg_kernel<<<BLD/4/256, 256>>>(V, O, IDX, SW);
    run_gemm(O, W + 3*DD*DD, sdst, bias + 3*DD, sprev, M, DD, DD, DD, 1, 0, 0, 0);
}

static void run_embed(const float* x, const float* Wp, float* y)
{
    // y[b,l,o] = sum_{j=0..2} x[b,(l+j-1)%L,:] @ Wp[:,:,j]^T
    for (int j = 0; j < 3; j++)
        run_gemm(x, Wp + j, y, nullptr, nullptr,
                 BB*LL, DD, DD, DD*3, 3, j - 1, 0, j > 0 ? 1 : 0);
}

extern "C" void kernel_launch(void* const* d_in, const int* in_sizes, int n_in,
                              void* d_out, int out_size)
{
    const float* x_s      = (const float*)d_in[0];
    const float* x_w      = (const float*)d_in[1];
    const float* wc1_W    = (const float*)d_in[2];
    const float* wc1_b    = (const float*)d_in[3];
    const float* wc2_W    = (const float*)d_in[4];
    const float* wc2_b    = (const float*)d_in[5];
    const float* attn_W   = (const float*)d_in[6];
    const float* attn_b   = (const float*)d_in[7];
    const float* wc1_proj = (const float*)d_in[8];
    const float* wc2_proj = (const float*)d_in[9];
    const float* conv1_W  = (const float*)d_in[10];
    const float* conv2_W  = (const float*)d_in[11];

    float* out_res = (float*)d_out;
    float* out_w   = out_res + BLD;

    float *Q, *K, *V, *O, *S, *T, *W1, *H, *R, *SW;
    int* IDX;
    cudaGetSymbolAddress((void**)&Q,   g_Q);
    cudaGetSymbolAddress((void**)&K,   g_K);
    cudaGetSymbolAddress((void**)&V,   g_V);
    cudaGetSymbolAddress((void**)&O,   g_O);
    cudaGetSymbolAddress((void**)&S,   g_S);
    cudaGetSymbolAddress((void**)&T,   g_T);
    cudaGetSymbolAddress((void**)&W1,  g_W1);
    cudaGetSymbolAddress((void**)&H,   g_H);
    cudaGetSymbolAddress((void**)&R,   g_R);
    cudaGetSymbolAddress((void**)&SW,  g_SW);
    cudaGetSymbolAddress((void**)&IDX, g_IDX);

    // 1) wc_decomp1: q=x_w, k=v=x_s;  S = x_s + attn(...)
    run_attn(x_w, x_s, wc1_W, wc1_b, x_s, S, Q, K, V, O, R, IDX, SW);

    // 2) W1 = token_embed(x_w, wc1_proj)
    run_embed(x_w, wc1_proj, W1);

    // 3) self-attention on S:  T = S + attn(S,S,S)
    run_attn(S, S, attn_W, attn_b, S, T, Q, K, V, O, R, IDX, SW);

    // 4) S = series_decomp(T)
    movavg_kernel<<<dim3(16, BB), 128>>>(T, S);

    // 5) wc_decomp2: q=W1, k=v=S;  T = S + attn(...)
    run_attn(W1, S, wc2_W, wc2_b, S, T, Q, K, V, O, R, IDX, SW);

    // 6) x_w_new = token_embed(W1, wc2_proj) -> second output
    run_embed(W1, wc2_proj, out_w);

    // 7) FFN: H = relu(T @ conv1_W^T); S = T + H @ conv2_W^T
    run_gemm(T, conv1_W, H, nullptr, nullptr, BB*LL, DFF, DD, DD, 1, 0, 1, 0);
    run_gemm(H, conv2_W, S, nullptr, T, BB*LL, DD, DFF, DFF, 1, 0, 0, 0);

    // 8) res = series_decomp(S) -> first output
    movavg_kernel<<<dim3(16, BB), 128>>>(S, out_res);
}

// round 4
// speedup vs baseline: 2.3615x; 2.3615x over previous
#include <cuda_runtime.h>
#include <cstdint>
#include <cstddef>

#define BB  16
#define LL  1536
#define DD  512
#define DFF 2048
#define BLD (BB*LL*DD)

// tiles
#define BM 128
#define BN 128
#define BK 32                         // floats = 128 bytes per row
#define A_TILE (BM*BK*4)              // 16384
#define STAGE_BYTES (2*A_TILE)        // 32768 (A then B)
#define NSTAGE 4
#define GEMM_SMEM (NSTAGE*STAGE_BYTES)  // 131072

// ---------------- device scratch ----------------
__device__ float g_Q[BLD];
__device__ float g_K[BLD];
__device__ float g_V[BLD];
__device__ float g_O[BLD];
__device__ float g_S[BLD];
__device__ float g_T[BLD];
__device__ float g_W1[BLD];
__device__ float g_H[(size_t)BB*LL*DFF];
__device__ float g_R[BB*LL];
__device__ float g_SW[BB*8];
__device__ int   g_IDX[8];
__device__ float g_WT[3*DD*DD];

// ---------------- PTX helpers ----------------
__device__ __forceinline__ uint32_t smem_u32(const void* p) {
    uint32_t a;
    asm("{ .reg .u64 t; cvta.to.shared.u64 t, %1; cvt.u32.u64 %0, t; }" : "=r"(a) : "l"(p));
    return a;
}
__device__ __forceinline__ void cp16(uint32_t s, const void* g) {
    asm volatile("cp.async.cg.shared.global [%0], [%1], 16;" :: "r"(s), "l"(g));
}
__device__ __forceinline__ void cp_commit() {
    asm volatile("cp.async.commit_group;" ::: "memory");
}
template<int N> __device__ __forceinline__ void cp_wait() {
    asm volatile("cp.async.wait_group %0;" :: "n"(N) : "memory");
}
__device__ __forceinline__ void mma_tf32(float* d, const uint32_t* a, const uint32_t* b) {
    asm volatile("mma.sync.aligned.m16n8k8.row.col.f32.tf32.tf32.f32 "
        "{%0,%1,%2,%3}, {%4,%5,%6,%7}, {%8,%9}, {%0,%1,%2,%3};"
        : "+f"(d[0]), "+f"(d[1]), "+f"(d[2]), "+f"(d[3])
        : "r"(a[0]), "r"(a[1]), "r"(a[2]), "r"(a[3]), "r"(b[0]), "r"(b[1]));
}
__device__ __forceinline__ uint32_t lds32(uint32_t a) {
    uint32_t v;
    asm volatile("ld.shared.b32 %0, [%1];" : "=r"(v) : "r"(a));
    return v;
}
__device__ __forceinline__ void split_tf32(uint32_t x, uint32_t& hi, uint32_t& lo) {
    float f = __uint_as_float(x);
    uint32_t h;
    asm("cvt.rna.tf32.f32 %0, %1;" : "=r"(h) : "f"(f));
    float l = f - __uint_as_float(h);
    hi = h; lo = __float_as_uint(l);
}
__device__ __forceinline__ uint32_t swz16(uint32_t o) { return o ^ ((o >> 3) & 0x70); }

// =====================================================================
// tf32 HMMA GEMM: C[M,N] = sum_pass A_pass[M,K] @ B_pass[N,K]^T (+bias)(+resid)(relu)
// npasses>1: embed conv; pass p circularly shifts A rows by (p-1) within each LL batch.
// PRECISE=1: 3xTF32 error-compensated (hi/lo split) for near-fp32 accuracy.
// 256 threads, 8 warps of 64x32; block 128x128; 4-stage cp.async pipeline.
// =====================================================================
template<int PRECISE>
__global__ __launch_bounds__(256, 1)
void gemm_mm(const float* __restrict__ A, const float* __restrict__ B,
             float* __restrict__ C, const float* __restrict__ bias,
             const float* __restrict__ resid,
             int N, int K, int npasses, int relu)
{
    extern __shared__ char smem[];
    const uint32_t sb = smem_u32(smem);
    const int tid = threadIdx.x;
    const int lane = tid & 31, wid = tid >> 5;
    const int wr = wid & 1, wc = wid >> 1;
    const int m0 = blockIdx.y * BM, n0 = blockIdx.x * BN;
    const int kSteps = K / BK;
    const int T = npasses * kSteps;

    // loader: 4 cp16 for A, 4 for B per thread
    int arow[4], achk[4];
#pragma unroll
    for (int u = 0; u < 4; u++) { int q = tid*4 + u; arow[u] = q >> 3; achk[u] = q & 7; }

    auto load_stage = [&](int t) {
        int pass = (npasses > 1) ? (t / kSteps) : 0;
        int k0 = (t - pass * kSteps) * BK;
        uint32_t sA = sb + (t & (NSTAGE-1)) * STAGE_BYTES;
        uint32_t sB = sA + A_TILE;
        const float* Bp = B + (size_t)pass * N * K;
#pragma unroll
        for (int u = 0; u < 4; u++) {
            int m = m0 + arow[u], rg = m;
            if (npasses > 1) {
                int b = m / LL, l = m - b * LL;
                l += pass - 1;
                if (l < 0) l += LL; else if (l >= LL) l -= LL;
                rg = b * LL + l;
            }
            cp16(sA + swz16(arow[u]*128 + achk[u]*16),
                 A + (size_t)rg * K + k0 + achk[u]*4);
        }
#pragma unroll
        for (int u = 0; u < 4; u++) {
            cp16(sB + swz16(arow[u]*128 + achk[u]*16),
                 Bp + (size_t)(n0 + arow[u]) * K + k0 + achk[u]*4);
        }
        cp_commit();
    };

    load_stage(0); load_stage(1); load_stage(2);

    float acc[4][4][4];
#pragma unroll
    for (int i = 0; i < 4; i++)
#pragma unroll
        for (int j = 0; j < 4; j++)
#pragma unroll
            for (int r = 0; r < 4; r++) acc[i][j][r] = 0.f;

    const int xr = (lane >> 2) << 4;          // swizzle XOR for both A and B frag rows
    int r0[4], nl[4];
#pragma unroll
    for (int i = 0; i < 4; i++) r0[i] = wr*64 + i*16 + (lane >> 2);
#pragma unroll
    for (int j = 0; j < 4; j++) nl[j] = wc*32 + j*8 + (lane >> 2);

    for (int t = 0; t < T; t++) {
        int rem = T - 1 - t;
        if (rem >= 2) cp_wait<2>(); else if (rem == 1) cp_wait<1>(); else cp_wait<0>();
        __syncthreads();
        if (t + 3 < T) load_stage(t + 3);

        uint32_t sA = sb + (t & (NSTAGE-1)) * STAGE_BYTES;
        uint32_t sB = sA + A_TILE;
#pragma unroll
        for (int s8 = 0; s8 < 4; s8++) {
            uint32_t c0x = (uint32_t)((s8*32) | ((lane & 3) * 4)) ^ xr;
            uint32_t af[4][4], bf[4][2];
#pragma unroll
            for (int i = 0; i < 4; i++) {
                uint32_t base = sA + r0[i]*128;
                af[i][0] = lds32(base + c0x);
                af[i][1] = lds32(base + 1024 + c0x);
                af[i][2] = lds32(base + (c0x ^ 16));
                af[i][3] = lds32(base + 1024 + (c0x ^ 16));
            }
#pragma unroll
            for (int j = 0; j < 4; j++) {
                uint32_t base = sB + nl[j]*128;
                bf[j][0] = lds32(base + c0x);
                bf[j][1] = lds32(base + (c0x ^ 16));
            }
            if (PRECISE) {
                uint32_t ah[4][4], al[4][4], bh[4][2], bl[4][2];
#pragma unroll
                for (int i = 0; i < 4; i++)
#pragma unroll
                    for (int q = 0; q < 4; q++) split_tf32(af[i][q], ah[i][q], al[i][q]);
#pragma unroll
                for (int j = 0; j < 4; j++)
#pragma unroll
                    for (int q = 0; q < 2; q++) split_tf32(bf[j][q], bh[j][q], bl[j][q]);
#pragma unroll
                for (int i = 0; i < 4; i++)
#pragma unroll
                    for (int j = 0; j < 4; j++) {
                        mma_tf32(acc[i][j], al[i], bh[j]);
                        mma_tf32(acc[i][j], ah[i], bl[j]);
                        mma_tf32(acc[i][j], ah[i], bh[j]);
                    }
            } else {
#pragma unroll
                for (int i = 0; i < 4; i++)
#pragma unroll
                    for (int j = 0; j < 4; j++)
                        mma_tf32(acc[i][j], af[i], bf[j]);
            }
        }
    }

    // epilogue: direct float2 stores (32B-coalesced per 4 lanes)
#pragma unroll
    for (int i = 0; i < 4; i++) {
        int mrow = m0 + wr*64 + i*16 + (lane >> 2);
#pragma unroll
        for (int j = 0; j < 4; j++) {
            int n = n0 + wc*32 + j*8 + 2*(lane & 3);
#pragma unroll
            for (int h = 0; h < 2; h++) {
                int mm = mrow + h*8;
                float vx = acc[i][j][2*h+0], vy = acc[i][j][2*h+1];
                if (bias)  { vx += bias[n]; vy += bias[n+1]; }
                if (resid) {
                    float2 rv = *reinterpret_cast<const float2*>(&resid[(size_t)mm*N + n]);
                    vx += rv.x; vy += rv.y;
                }
                if (relu) { vx = fmaxf(vx, 0.f); vy = fmaxf(vy, 0.f); }
                float2 v; v.x = vx; v.y = vy;
                *reinterpret_cast<float2*>(&C[(size_t)mm*N + n]) = v;
            }
        }
    }
}

// =====================================================================
// corr: r[b,tau] += diagonal sums of Q_b K_b^T over 128x128 tiles
// =====================================================================
__global__ __launch_bounds__(256, 1)
void corr_mm(const float* __restrict__ Q, const float* __restrict__ Kb,
             float* __restrict__ r)
{
    extern __shared__ char smem[];
    const uint32_t sb = smem_u32(smem);
    const int tid = threadIdx.x;
    const int lane = tid & 31, wid = tid >> 5;
    const int wr = wid & 1, wc = wid >> 1;
    const int b = blockIdx.z;
    const int i0 = blockIdx.y * BM, j0 = blockIdx.x * BN;
    const float* Qb = Q + (size_t)b * LL * DD;
    const float* KB = Kb + (size_t)b * LL * DD;
    const int T = DD / BK;   // 16

    int arow[4], achk[4];
#pragma unroll
    for (int u = 0; u < 4; u++) { int q = tid*4 + u; arow[u] = q >> 3; achk[u] = q & 7; }

    auto load_stage = [&](int t) {
        int k0 = t * BK;
        uint32_t sA = sb + (t & (NSTAGE-1)) * STAGE_BYTES;
        uint32_t sB = sA + A_TILE;
#pragma unroll
        for (int u = 0; u < 4; u++)
            cp16(sA + swz16(arow[u]*128 + achk[u]*16),
                 Qb + (size_t)(i0 + arow[u]) * DD + k0 + achk[u]*4);
#pragma unroll
        for (int u = 0; u < 4; u++)
            cp16(sB + swz16(arow[u]*128 + achk[u]*16),
                 KB + (size_t)(j0 + arow[u]) * DD + k0 + achk[u]*4);
        cp_commit();
    };

    load_stage(0); load_stage(1); load_stage(2);

    float acc[4][4][4];
#pragma unroll
    for (int i = 0; i < 4; i++)
#pragma unroll
        for (int j = 0; j < 4; j++)
#pragma unroll
            for (int q = 0; q < 4; q++) acc[i][j][q] = 0.f;

    const int xr = (lane >> 2) << 4;
    int r0[4], nl[4];
#pragma unroll
    for (int i = 0; i < 4; i++) r0[i] = wr*64 + i*16 + (lane >> 2);
#pragma unroll
    for (int j = 0; j < 4; j++) nl[j] = wc*32 + j*8 + (lane >> 2);

    for (int t = 0; t < T; t++) {
        int rem = T - 1 - t;
        if (rem >= 2) cp_wait<2>(); else if (rem == 1) cp_wait<1>(); else cp_wait<0>();
        __syncthreads();
        if (t + 3 < T) load_stage(t + 3);

        uint32_t sA = sb + (t & (NSTAGE-1)) * STAGE_BYTES;
        uint32_t sB = sA + A_TILE;
#pragma unroll
        for (int s8 = 0; s8 < 4; s8++) {
            uint32_t c0x = (uint32_t)((s8*32) | ((lane & 3) * 4)) ^ xr;
            uint32_t af[4][4], bf[4][2];
#pragma unroll
            for (int i = 0; i < 4; i++) {
                uint32_t base = sA + r0[i]*128;
                af[i][0] = lds32(base + c0x);
                af[i][1] = lds32(base + 1024 + c0x);
                af[i][2] = lds32(base + (c0x ^ 16));
                af[i][3] = lds32(base + 1024 + (c0x ^ 16));
            }
#pragma unroll
            for (int j = 0; j < 4; j++) {
                uint32_t base = sB + nl[j]*128;
                bf[j][0] = lds32(base + c0x);
                bf[j][1] = lds32(base + (c0x ^ 16));
            }
#pragma unroll
            for (int i = 0; i < 4; i++)
#pragma unroll
                for (int j = 0; j < 4; j++)
                    mma_tf32(acc[i][j], af[i], bf[j]);
        }
    }

    // spill tile to smem (stride 130 keeps float2 alignment), then diagonal-reduce
    __syncthreads();
    float* Cs = (float*)smem;   // 128 x 130
#pragma unroll
    for (int i = 0; i < 4; i++) {
        int mrow = wr*64 + i*16 + (lane >> 2);
#pragma unroll
        for (int j = 0; j < 4; j++) {
            int n = wc*32 + j*8 + 2*(lane & 3);
#pragma unroll
            for (int h = 0; h < 2; h++) {
                float2 v; v.x = acc[i][j][2*h+0]; v.y = acc[i][j][2*h+1];
                *reinterpret_cast<float2*>(&Cs[(mrow + h*8)*130 + n]) = v;
            }
        }
    }
    __syncthreads();

    if (tid < 255) {
        int d = tid - 127;                 // i - j
        int ilo = d > 0 ? d : 0;
        int ihi = d < 0 ? 127 + d : 127;
        float s = 0.f;
        for (int i = ilo; i <= ihi; i++) s += Cs[i*130 + (i - d)];
        int tau = (i0 - j0 + d) % LL;
        if (tau < 0) tau += LL;
        atomicAdd(&r[(size_t)b * LL + tau], s);
    }
}

// ---------------- small kernels ----------------
__global__ void zero_kernel(float* p, int n)
{
    int i = blockIdx.x * 256 + threadIdx.x;
    if (i < n) p[i] = 0.f;
}

__global__ void wtrans_kernel(const float* __restrict__ Wp, float* __restrict__ Wt)
{
    int idx = blockIdx.x * 256 + threadIdx.x;   // 3*512*512
    int p = idx / (DD*DD);
    int rr = idx - p * (DD*DD);
    int n = rr >> 9, k = rr & 511;
    Wt[idx] = Wp[n * (DD*3) + k * 3 + p];
}

__global__ void topk_kernel(const float* __restrict__ r, int* __restrict__ gidx,
                            float* __restrict__ gsw)
{
    __shared__ float gv[LL];
    __shared__ float rv[256];
    __shared__ int   ri[256];
    __shared__ int   sidx[7];
    const int tid = threadIdx.x;

    for (int t = tid; t < LL; t += 256) {
        float s = 0.f;
        for (int b = 0; b < BB; b++) s += r[(size_t)b*LL + t];
        gv[t] = s;
    }
    __syncthreads();

    for (int it = 0; it < 7; it++) {
        float bv = -3.4e38f; int bi = 0;
        for (int t = tid; t < LL; t += 256) {
            float v = gv[t];
            if (v > bv) { bv = v; bi = t; }
        }
        rv[tid] = bv; ri[tid] = bi;
        __syncthreads();
        for (int s = 128; s > 0; s >>= 1) {
            if (tid < s) {
                if (rv[tid+s] > rv[tid] ||
                    (rv[tid+s] == rv[tid] && ri[tid+s] < ri[tid])) {
                    rv[tid] = rv[tid+s]; ri[tid] = ri[tid+s];
                }
            }
            __syncthreads();
        }
        if (tid == 0) { sidx[it] = ri[0]; gv[ri[0]] = -3.4e38f; }
        __syncthreads();
    }

    if (tid < 7) gidx[tid] = sidx[tid];
    if (tid < BB) {
        float w[7], m = -3.4e38f;
        for (int i = 0; i < 7; i++) {
            w[i] = r[(size_t)tid*LL + sidx[i]] * (1.0f / (float)DD);
            m = fmaxf(m, w[i]);
        }
        float sum = 0.f;
        for (int i = 0; i < 7; i++) { w[i] = expf(w[i] - m); sum += w[i]; }
        float inv = 1.0f / sum;
        for (int i = 0; i < 7; i++) gsw[tid*7 + i] = w[i] * inv;
    }
}

__global__ __launch_bounds__(256)
void agg_kernel(const float* __restrict__ V, float* __restrict__ O,
                const int* __restrict__ idxp, const float* __restrict__ swp)
{
    int g = blockIdx.x * 256 + threadIdx.x;
    int d4 = g & 127;
    int l  = (g >> 7) % LL;
    int b  = g / (LL * 128);

    int   idx[7];
    float w[7];
#pragma unroll
    for (int i = 0; i < 7; i++) { idx[i] = idxp[i]; w[i] = swp[b*7 + i]; }

    const float4* Vb = reinterpret_cast<const float4*>(V + (size_t)b * LL * DD);
    float4 acc = {0.f, 0.f, 0.f, 0.f};
#pragma unroll
    for (int i = 0; i < 7; i++) {
        int ls = l + idx[i];
        if (ls >= LL) ls -= LL;
        float4 v = Vb[(size_t)ls * 128 + d4];
        acc.x += w[i] * v.x; acc.y += w[i] * v.y;
        acc.z += w[i] * v.z; acc.w += w[i] * v.w;
    }
    reinterpret_cast<float4*>(O)[g] = acc;
}

__global__ __launch_bounds__(128)
void movavg_kernel(const float* __restrict__ X, float* __restrict__ out)
{
    const int b  = blockIdx.y;
    const int l0 = blockIdx.x * 96;
    const int d4 = threadIdx.x;
    const float4* x = reinterpret_cast<const float4*>(X + (size_t)b * LL * DD) + d4;
    float4* o = reinterpret_cast<float4*>(out + (size_t)b * LL * DD) + d4;

    float4 s = {0.f, 0.f, 0.f, 0.f};
    for (int j = -12; j <= 12; j++) {
        int lc = l0 + j;
        if (lc < 0) lc = 0;
        if (lc > LL-1) lc = LL-1;
        float4 v = x[(size_t)lc * 128];
        s.x += v.x; s.y += v.y; s.z += v.z; s.w += v.w;
    }
    const float inv = 1.0f / 25.0f;
    for (int t = 0; t < 96; t++) {
        int l = l0 + t;
        float4 xc = x[(size_t)l * 128];
        float4 rr;
        rr.x = xc.x - s.x * inv; rr.y = xc.y - s.y * inv;
        rr.z = xc.z - s.z * inv; rr.w = xc.w - s.w * inv;
        o[(size_t)l * 128] = rr;
        int la = l + 13; if (la > LL-1) la = LL-1;
        int lr = l - 12; if (lr < 0)    lr = 0;
        float4 va = x[(size_t)la * 128];
        float4 vr = x[(size_t)lr * 128];
        s.x += va.x - vr.x; s.y += va.y - vr.y;
        s.z += va.z - vr.z; s.w += va.w - vr.w;
    }
}

// ---------------- host orchestration ----------------
static void run_gemm(const float* A, const float* B, float* C,
                     const float* bias, const float* resid,
                     int N, int K, int npasses, int relu, int precise = 0)
{
    dim3 grid(N / BN, (BB*LL) / BM);
    if (precise)
        gemm_mm<1><<<grid, 256, GEMM_SMEM>>>(A, B, C, bias, resid, N, K, npasses, relu);
    else
        gemm_mm<0><<<grid, 256, GEMM_SMEM>>>(A, B, C, bias, resid, N, K, npasses, relu);
}

static void run_attn(const float* qsrc, const float* kvsrc,
                     const float* W, const float* bias,
                     const float* sprev, float* sdst,
                     float* Q, float* K, float* V, float* O,
                     float* R, int* IDX, float* SW)
{
    run_gemm(qsrc,  W + 0*DD*DD, Q, bias + 0*DD, nullptr, DD, DD, 1, 0);
    run_gemm(kvsrc, W + 1*DD*DD, K, bias + 1*DD, nullptr, DD, DD, 1, 0);
    run_gemm(kvsrc, W + 2*DD*DD, V, bias + 2*DD, nullptr, DD, DD, 1, 0);
    zero_kernel<<<(BB*LL + 255)/256, 256>>>(R, BB*LL);
    dim3 cg(LL/BN, LL/BM, BB);
    corr_mm<<<cg, 256, GEMM_SMEM>>>(Q, K, R);
    topk_kernel<<<1, 256>>>(R, IDX, SW);
    agg_kernel<<<BLD/4/256, 256>>>(V, O, IDX, SW);
    run_gemm(O, W + 3*DD*DD, sdst, bias + 3*DD, sprev, DD, DD, 1, 0);
}

extern "C" void kernel_launch(void* const* d_in, const int* in_sizes, int n_in,
                              void* d_out, int out_size)
{
    const float* x_s      = (const float*)d_in[0];
    const float* x_w      = (const float*)d_in[1];
    const float* wc1_W    = (const float*)d_in[2];
    const float* wc1_b    = (const float*)d_in[3];
    const float* wc2_W    = (const float*)d_in[4];
    const float* wc2_b    = (const float*)d_in[5];
    const float* attn_W   = (const float*)d_in[6];
    const float* attn_b   = (const float*)d_in[7];
    const float* wc1_proj = (const float*)d_in[8];
    const float* wc2_proj = (const float*)d_in[9];
    const float* conv1_W  = (const float*)d_in[10];
    const float* conv2_W  = (const float*)d_in[11];

    float* out_res = (float*)d_out;
    float* out_w   = out_res + BLD;

    cudaFuncSetAttribute(gemm_mm<0>, cudaFuncAttributeMaxDynamicSharedMemorySize, GEMM_SMEM);
    cudaFuncSetAttribute(gemm_mm<1>, cudaFuncAttributeMaxDynamicSharedMemorySize, GEMM_SMEM);
    cudaFuncSetAttribute(corr_mm, cudaFuncAttributeMaxDynamicSharedMemorySize, GEMM_SMEM);

    float *Q, *K, *V, *O, *S, *T, *W1, *H, *R, *SW, *WT;
    int* IDX;
    cudaGetSymbolAddress((void**)&Q,   g_Q);
    cudaGetSymbolAddress((void**)&K,   g_K);
    cudaGetSymbolAddress((void**)&V,   g_V);
    cudaGetSymbolAddress((void**)&O,   g_O);
    cudaGetSymbolAddress((void**)&S,   g_S);
    cudaGetSymbolAddress((void**)&T,   g_T);
    cudaGetSymbolAddress((void**)&W1,  g_W1);
    cudaGetSymbolAddress((void**)&H,   g_H);
    cudaGetSymbolAddress((void**)&R,   g_R);
    cudaGetSymbolAddress((void**)&SW,  g_SW);
    cudaGetSymbolAddress((void**)&IDX, g_IDX);
    cudaGetSymbolAddress((void**)&WT,  g_WT);

    // 1) wc_decomp1: q=x_w, k=v=x_s;  S = x_s + attn(...)
    run_attn(x_w, x_s, wc1_W, wc1_b, x_s, S, Q, K, V, O, R, IDX, SW);

    // 2) W1 = token_embed(x_w, wc1_proj)  (3 register-accumulated shifted passes, 3xTF32)
    wtrans_kernel<<<3*DD*DD/256, 256>>>(wc1_proj, WT);
    run_gemm(x_w, WT, W1, nullptr, nullptr, DD, DD, 3, 0, 1);

    // 3) self-attention on S:  T = S + attn(S,S,S)
    run_attn(S, S, attn_W, attn_b, S, T, Q, K, V, O, R, IDX, SW);

    // 4) S = series_decomp(T)
    movavg_kernel<<<dim3(16, BB), 128>>>(T, S);

    // 5) wc_decomp2: q=W1, k=v=S;  T = S + attn(...)
    run_attn(W1, S, wc2_W, wc2_b, S, T, Q, K, V, O, R, IDX, SW);

    // 6) x_w_new = token_embed(W1, wc2_proj) -> second output (3xTF32)
    wtrans_kernel<<<3*DD*DD/256, 256>>>(wc2_proj, WT);
    run_gemm(W1, WT, out_w, nullptr, nullptr, DD, DD, 3, 0, 1);

    // 7) FFN: H = relu(T @ conv1_W^T); S = T + H @ conv2_W^T
    run_gemm(T, conv1_W, H, nullptr, nullptr, DFF, DD, 1, 1);
    run_gemm(H, conv2_W, S, nullptr, T, DD, DFF, 1, 0);

    // 8) res = series_decomp(S) -> first output
    movavg_kernel<<<dim3(16, BB), 128>>>(S, out_res);
}

// round 5
// speedup vs baseline: 2.8431x; 1.2040x over previous
#include <cuda_runtime.h>
#include <cstdint>
#include <cstddef>

#define BB  16
#define LL  1536
#define DD  512
#define DFF 2048
#define BLD (BB*LL*DD)

// tiles
#define BM 128
#define BN 128
#define BK 32                         // floats = 128 bytes per row
#define A_TILE (BM*BK*4)              // 16384
#define STAGE_BYTES (2*A_TILE)        // 32768 (A then B)
#define NSTAGE 3
#define GEMM_SMEM (NSTAGE*STAGE_BYTES)  // 98304

// ---------------- device scratch ----------------
__device__ float g_Q[BLD];
__device__ float g_K[BLD];
__device__ float g_V[BLD];
__device__ float g_O[BLD];
__device__ float g_S[BLD];
__device__ float g_T[BLD];
__device__ float g_W1[BLD];
__device__ float g_H[(size_t)BB*LL*DFF];
__device__ float g_R[BB*LL];
__device__ float g_SW[BB*8];
__device__ int   g_IDX[8];
__device__ float g_WT[3*DD*DD];

// ---------------- PTX helpers ----------------
__device__ __forceinline__ uint32_t smem_u32(const void* p) {
    uint32_t a;
    asm("{ .reg .u64 t; cvta.to.shared.u64 t, %1; cvt.u32.u64 %0, t; }" : "=r"(a) : "l"(p));
    return a;
}
__device__ __forceinline__ void cp16(uint32_t s, const void* g) {
    asm volatile("cp.async.cg.shared.global [%0], [%1], 16;" :: "r"(s), "l"(g));
}
__device__ __forceinline__ void cp_commit() {
    asm volatile("cp.async.commit_group;" ::: "memory");
}
template<int N> __device__ __forceinline__ void cp_wait() {
    asm volatile("cp.async.wait_group %0;" :: "n"(N) : "memory");
}
__device__ __forceinline__ void mma_tf32(float* d, const uint32_t* a, const uint32_t* b) {
    asm volatile("mma.sync.aligned.m16n8k8.row.col.f32.tf32.tf32.f32 "
        "{%0,%1,%2,%3}, {%4,%5,%6,%7}, {%8,%9}, {%0,%1,%2,%3};"
        : "+f"(d[0]), "+f"(d[1]), "+f"(d[2]), "+f"(d[3])
        : "r"(a[0]), "r"(a[1]), "r"(a[2]), "r"(a[3]), "r"(b[0]), "r"(b[1]));
}
__device__ __forceinline__ void ldsm4(uint32_t& r0, uint32_t& r1, uint32_t& r2, uint32_t& r3,
                                      uint32_t a) {
    asm volatile("ldmatrix.sync.aligned.m8n8.x4.shared.b16 {%0,%1,%2,%3}, [%4];"
        : "=r"(r0), "=r"(r1), "=r"(r2), "=r"(r3) : "r"(a));
}
__device__ __forceinline__ void split_tf32(uint32_t& x, uint32_t& lo) {
    float f = __uint_as_float(x);
    uint32_t h;
    asm("cvt.rna.tf32.f32 %0, %1;" : "=r"(h) : "f"(f));
    lo = __float_as_uint(f - __uint_as_float(h));
    x = h;
}
__device__ __forceinline__ uint32_t swz16(uint32_t o) { return o ^ ((o >> 3) & 0x70); }

// =====================================================================
// tf32 HMMA GEMM: C[M,N] = sum_pass A_pass[M,K] @ B_pass[N,K]^T (+bias)(+resid)(relu)
// npasses>1: embed conv; pass p circularly shifts A rows by (p-1) within each LL batch.
// PRECISE=1: 3xTF32 error-compensated (hi/lo split) for near-fp32 accuracy.
// 256 threads, 8 warps of 64x32; block 128x128; 3-stage cp.async pipeline; occ 2.
// Fragment loads via ldmatrix.x4 (tf32 frag layout == m8n8.b16 distribution on fp32 words).
// =====================================================================
template<int PRECISE>
__global__ __launch_bounds__(256, 2)
void gemm_mm(const float* __restrict__ A, const float* __restrict__ B,
             float* __restrict__ C, const float* __restrict__ bias,
             const float* __restrict__ resid,
             int N, int K, int npasses, int relu)
{
    extern __shared__ char smem[];
    const uint32_t sb = smem_u32(smem);
    const int tid = threadIdx.x;
    const int lane = tid & 31, wid = tid >> 5;
    const int wr = wid & 1, wc = wid >> 1;
    const int m0 = blockIdx.y * BM, n0 = blockIdx.x * BN;
    const int kSteps = K / BK;
    const int T = npasses * kSteps;

    // loader: 4 cp16 for A, 4 for B per thread
    int arow[4], achk[4];
#pragma unroll
    for (int u = 0; u < 4; u++) { int q = tid*4 + u; arow[u] = q >> 3; achk[u] = q & 7; }

    auto load_stage = [&](int t) {
        int pass = (npasses > 1) ? (t / kSteps) : 0;
        int k0 = (t - pass * kSteps) * BK;
        uint32_t sA = sb + (t % NSTAGE) * STAGE_BYTES;
        uint32_t sB = sA + A_TILE;
        const float* Bp = B + (size_t)pass * N * K;
#pragma unroll
        for (int u = 0; u < 4; u++) {
            int m = m0 + arow[u], rg = m;
            if (npasses > 1) {
                int b = m / LL, l = m - b * LL;
                l += pass - 1;
                if (l < 0) l += LL; else if (l >= LL) l -= LL;
                rg = b * LL + l;
            }
            cp16(sA + swz16(arow[u]*128 + achk[u]*16),
                 A + (size_t)rg * K + k0 + achk[u]*4);
        }
#pragma unroll
        for (int u = 0; u < 4; u++) {
            cp16(sB + swz16(arow[u]*128 + achk[u]*16),
                 Bp + (size_t)(n0 + arow[u]) * K + k0 + achk[u]*4);
        }
        cp_commit();
    };

    load_stage(0); load_stage(1);

    float acc[4][4][4];
#pragma unroll
    for (int i = 0; i < 4; i++)
#pragma unroll
        for (int j = 0; j < 4; j++)
#pragma unroll
            for (int r = 0; r < 4; r++) acc[i][j][r] = 0.f;

    // ldmatrix addressing
    const int sw = lane & 7;                       // row%8 (swizzle xor)
    int aoffs[4], boffs[2];
#pragma unroll
    for (int i = 0; i < 4; i++)
        aoffs[i] = (wr*64 + i*16 + ((lane >> 3) & 1)*8 + sw) * 128;
#pragma unroll
    for (int jp = 0; jp < 2; jp++)
        boffs[jp] = (wc*32 + jp*16 + ((lane >> 4) & 1)*8 + sw) * 128;
    const int aC = lane >> 4;            // A chunk sub-index (0..1)
    const int bC = (lane >> 3) & 1;      // B chunk sub-index (0..1)

    for (int t = 0; t < T; t++) {
        int rem = T - 1 - t;
        if (rem >= 1) cp_wait<1>(); else cp_wait<0>();
        __syncthreads();
        if (t + 2 < T) load_stage(t + 2);

        uint32_t sA = sb + (t % NSTAGE) * STAGE_BYTES;
        uint32_t sB = sA + A_TILE;
#pragma unroll
        for (int s8 = 0; s8 < 4; s8++) {
            uint32_t af[4][4], bf[4][2];
            uint32_t ach = (uint32_t)(((s8*2 + aC) ^ sw) << 4);
            uint32_t bch = (uint32_t)(((s8*2 + bC) ^ sw) << 4);
#pragma unroll
            for (int i = 0; i < 4; i++)
                ldsm4(af[i][0], af[i][1], af[i][2], af[i][3], sA + aoffs[i] + ach);
#pragma unroll
            for (int jp = 0; jp < 2; jp++)
                ldsm4(bf[2*jp][0], bf[2*jp][1], bf[2*jp+1][0], bf[2*jp+1][1],
                      sB + boffs[jp] + bch);
            if (PRECISE) {
                uint32_t al[4][4], bl[4][2];
#pragma unroll
                for (int i = 0; i < 4; i++)
#pragma unroll
                    for (int q = 0; q < 4; q++) split_tf32(af[i][q], al[i][q]);
#pragma unroll
                for (int j = 0; j < 4; j++)
#pragma unroll
                    for (int q = 0; q < 2; q++) split_tf32(bf[j][q], bl[j][q]);
#pragma unroll
                for (int i = 0; i < 4; i++)
#pragma unroll
                    for (int j = 0; j < 4; j++) {
                        mma_tf32(acc[i][j], al[i], bf[j]);
                        mma_tf32(acc[i][j], af[i], bl[j]);
                        mma_tf32(acc[i][j], af[i], bf[j]);
                    }
            } else {
#pragma unroll
                for (int i = 0; i < 4; i++)
#pragma unroll
                    for (int j = 0; j < 4; j++)
                        mma_tf32(acc[i][j], af[i], bf[j]);
            }
        }
    }

    // epilogue: direct float2 stores (32B-coalesced per 4 lanes)
#pragma unroll
    for (int i = 0; i < 4; i++) {
        int mrow = m0 + wr*64 + i*16 + (lane >> 2);
#pragma unroll
        for (int j = 0; j < 4; j++) {
            int n = n0 + wc*32 + j*8 + 2*(lane & 3);
#pragma unroll
            for (int h = 0; h < 2; h++) {
                int mm = mrow + h*8;
                float vx = acc[i][j][2*h+0], vy = acc[i][j][2*h+1];
                if (bias)  { vx += bias[n]; vy += bias[n+1]; }
                if (resid) {
                    float2 rv = *reinterpret_cast<const float2*>(&resid[(size_t)mm*N + n]);
                    vx += rv.x; vy += rv.y;
                }
                if (relu) { vx = fmaxf(vx, 0.f); vy = fmaxf(vy, 0.f); }
                float2 v; v.x = vx; v.y = vy;
                *reinterpret_cast<float2*>(&C[(size_t)mm*N + n]) = v;
            }
        }
    }
}

// =====================================================================
// corr: r[b,tau] += diagonal sums of Q_b K_b^T over 128x128 tiles
// =====================================================================
__global__ __launch_bounds__(256, 2)
void corr_mm(const float* __restrict__ Q, const float* __restrict__ Kb,
             float* __restrict__ r)
{
    extern __shared__ char smem[];
    const uint32_t sb = smem_u32(smem);
    const int tid = threadIdx.x;
    const int lane = tid & 31, wid = tid >> 5;
    const int wr = wid & 1, wc = wid >> 1;
    const int b = blockIdx.z;
    const int i0 = blockIdx.y * BM, j0 = blockIdx.x * BN;
    const float* Qb = Q + (size_t)b * LL * DD;
    const float* KB = Kb + (size_t)b * LL * DD;
    const int T = DD / BK;   // 16

    int arow[4], achk[4];
#pragma unroll
    for (int u = 0; u < 4; u++) { int q = tid*4 + u; arow[u] = q >> 3; achk[u] = q & 7; }

    auto load_stage = [&](int t) {
        int k0 = t * BK;
        uint32_t sA = sb + (t % NSTAGE) * STAGE_BYTES;
        uint32_t sB = sA + A_TILE;
#pragma unroll
        for (int u = 0; u < 4; u++)
            cp16(sA + swz16(arow[u]*128 + achk[u]*16),
                 Qb + (size_t)(i0 + arow[u]) * DD + k0 + achk[u]*4);
#pragma unroll
        for (int u = 0; u < 4; u++)
            cp16(sB + swz16(arow[u]*128 + achk[u]*16),
                 KB + (size_t)(j0 + arow[u]) * DD + k0 + achk[u]*4);
        cp_commit();
    };

    load_stage(0); load_stage(1);

    float acc[4][4][4];
#pragma unroll
    for (int i = 0; i < 4; i++)
#pragma unroll
        for (int j = 0; j < 4; j++)
#pragma unroll
            for (int q = 0; q < 4; q++) acc[i][j][q] = 0.f;

    const int sw = lane & 7;
    int aoffs[4], boffs[2];
#pragma unroll
    for (int i = 0; i < 4; i++)
        aoffs[i] = (wr*64 + i*16 + ((lane >> 3) & 1)*8 + sw) * 128;
#pragma unroll
    for (int jp = 0; jp < 2; jp++)
        boffs[jp] = (wc*32 + jp*16 + ((lane >> 4) & 1)*8 + sw) * 128;
    const int aC = lane >> 4;
    const int bC = (lane >> 3) & 1;

    for (int t = 0; t < T; t++) {
        int rem = T - 1 - t;
        if (rem >= 1) cp_wait<1>(); else cp_wait<0>();
        __syncthreads();
        if (t + 2 < T) load_stage(t + 2);

        uint32_t sA = sb + (t % NSTAGE) * STAGE_BYTES;
        uint32_t sB = sA + A_TILE;
#pragma unroll
        for (int s8 = 0; s8 < 4; s8++) {
            uint32_t af[4][4], bf[4][2];
            uint32_t ach = (uint32_t)(((s8*2 + aC) ^ sw) << 4);
            uint32_t bch = (uint32_t)(((s8*2 + bC) ^ sw) << 4);
#pragma unroll
            for (int i = 0; i < 4; i++)
                ldsm4(af[i][0], af[i][1], af[i][2], af[i][3], sA + aoffs[i] + ach);
#pragma unroll
            for (int jp = 0; jp < 2; jp++)
                ldsm4(bf[2*jp][0], bf[2*jp][1], bf[2*jp+1][0], bf[2*jp+1][1],
                      sB + boffs[jp] + bch);
#pragma unroll
            for (int i = 0; i < 4; i++)
#pragma unroll
                for (int j = 0; j < 4; j++)
                    mma_tf32(acc[i][j], af[i], bf[j]);
        }
    }

    // spill tile to smem (stride 130 keeps float2 alignment), then diagonal-reduce
    __syncthreads();
    float* Cs = (float*)smem;   // 128 x 130
#pragma unroll
    for (int i = 0; i < 4; i++) {
        int mrow = wr*64 + i*16 + (lane >> 2);
#pragma unroll
        for (int j = 0; j < 4; j++) {
            int n = wc*32 + j*8 + 2*(lane & 3);
#pragma unroll
            for (int h = 0; h < 2; h++) {
                float2 v; v.x = acc[i][j][2*h+0]; v.y = acc[i][j][2*h+1];
                *reinterpret_cast<float2*>(&Cs[(mrow + h*8)*130 + n]) = v;
            }
        }
    }
    __syncthreads();

    if (tid < 255) {
        int d = tid - 127;                 // i - j
        int ilo = d > 0 ? d : 0;
        int ihi = d < 0 ? 127 + d : 127;
        float s = 0.f;
        for (int i = ilo; i <= ihi; i++) s += Cs[i*130 + (i - d)];
        int tau = (i0 - j0 + d) % LL;
        if (tau < 0) tau += LL;
        atomicAdd(&r[(size_t)b * LL + tau], s);
    }
}

// ---------------- small kernels ----------------
__global__ void zero_kernel(float* p, int n)
{
    int i = blockIdx.x * 256 + threadIdx.x;
    if (i < n) p[i] = 0.f;
}

__global__ void wtrans_kernel(const float* __restrict__ Wp, float* __restrict__ Wt)
{
    int idx = blockIdx.x * 256 + threadIdx.x;   // 3*512*512
    int p = idx / (DD*DD);
    int rr = idx - p * (DD*DD);
    int n = rr >> 9, k = rr & 511;
    Wt[idx] = Wp[n * (DD*3) + k * 3 + p];
}

__global__ void topk_kernel(const float* __restrict__ r, int* __restrict__ gidx,
                            float* __restrict__ gsw)
{
    __shared__ float gv[LL];
    __shared__ float rv[256];
    __shared__ int   ri[256];
    __shared__ int   sidx[7];
    const int tid = threadIdx.x;

    for (int t = tid; t < LL; t += 256) {
        float s = 0.f;
        for (int b = 0; b < BB; b++) s += r[(size_t)b*LL + t];
        gv[t] = s;
    }
    __syncthreads();

    for (int it = 0; it < 7; it++) {
        float bv = -3.4e38f; int bi = 0;
        for (int t = tid; t < LL; t += 256) {
            float v = gv[t];
            if (v > bv) { bv = v; bi = t; }
        }
        rv[tid] = bv; ri[tid] = bi;
        __syncthreads();
        for (int s = 128; s > 0; s >>= 1) {
            if (tid < s) {
                if (rv[tid+s] > rv[tid] ||
                    (rv[tid+s] == rv[tid] && ri[tid+s] < ri[tid])) {
                    rv[tid] = rv[tid+s]; ri[tid] = ri[tid+s];
                }
            }
            __syncthreads();
        }
        if (tid == 0) { sidx[it] = ri[0]; gv[ri[0]] = -3.4e38f; }
        __syncthreads();
    }

    if (tid < 7) gidx[tid] = sidx[tid];
    if (tid < BB) {
        float w[7], m = -3.4e38f;
        for (int i = 0; i < 7; i++) {
            w[i] = r[(size_t)tid*LL + sidx[i]] * (1.0f / (float)DD);
            m = fmaxf(m, w[i]);
        }
        float sum = 0.f;
        for (int i = 0; i < 7; i++) { w[i] = expf(w[i] - m); sum += w[i]; }
        float inv = 1.0f / sum;
        for (int i = 0; i < 7; i++) gsw[tid*7 + i] = w[i] * inv;
    }
}

__global__ __launch_bounds__(256)
void agg_kernel(const float* __restrict__ V, float* __restrict__ O,
                const int* __restrict__ idxp, const float* __restrict__ swp)
{
    int g = blockIdx.x * 256 + threadIdx.x;
    int d4 = g & 127;
    int l  = (g >> 7) % LL;
    int b  = g / (LL * 128);

    int   idx[7];
    float w[7];
#pragma unroll
    for (int i = 0; i < 7; i++) { idx[i] = idxp[i]; w[i] = swp[b*7 + i]; }

    const float4* Vb = reinterpret_cast<const float4*>(V + (size_t)b * LL * DD);
    float4 acc = {0.f, 0.f, 0.f, 0.f};
#pragma unroll
    for (int i = 0; i < 7; i++) {
        int ls = l + idx[i];
        if (ls >= LL) ls -= LL;
        float4 v = Vb[(size_t)ls * 128 + d4];
        acc.x += w[i] * v.x; acc.y += w[i] * v.y;
        acc.z += w[i] * v.z; acc.w += w[i] * v.w;
    }
    reinterpret_cast<float4*>(O)[g] = acc;
}

__global__ __launch_bounds__(128)
void movavg_kernel(const float* __restrict__ X, float* __restrict__ out)
{
    const int b  = blockIdx.y;
    const int l0 = blockIdx.x * 96;
    const int d4 = threadIdx.x;
    const float4* x = reinterpret_cast<const float4*>(X + (size_t)b * LL * DD) + d4;
    float4* o = reinterpret_cast<float4*>(out + (size_t)b * LL * DD) + d4;

    float4 s = {0.f, 0.f, 0.f, 0.f};
    for (int j = -12; j <= 12; j++) {
        int lc = l0 + j;
        if (lc < 0) lc = 0;
        if (lc > LL-1) lc = LL-1;
        float4 v = x[(size_t)lc * 128];
        s.x += v.x; s.y += v.y; s.z += v.z; s.w += v.w;
    }
    const float inv = 1.0f / 25.0f;
    for (int t = 0; t < 96; t++) {
        int l = l0 + t;
        float4 xc = x[(size_t)l * 128];
        float4 rr;
        rr.x = xc.x - s.x * inv; rr.y = xc.y - s.y * inv;
        rr.z = xc.z - s.z * inv; rr.w = xc.w - s.w * inv;
        o[(size_t)l * 128] = rr;
        int la = l + 13; if (la > LL-1) la = LL-1;
        int lr = l - 12; if (lr < 0)    lr = 0;
        float4 va = x[(size_t)la * 128];
        float4 vr = x[(size_t)lr * 128];
        s.x += va.x - vr.x; s.y += va.y - vr.y;
        s.z += va.z - vr.z; s.w += va.w - vr.w;
    }
}

// ---------------- host orchestration ----------------
static void run_gemm(const float* A, const float* B, float* C,
                     const float* bias, const float* resid,
                     int N, int K, int npasses, int relu, int precise = 0)
{
    dim3 grid(N / BN, (BB*LL) / BM);
    if (precise)
        gemm_mm<1><<<grid, 256, GEMM_SMEM>>>(A, B, C, bias, resid, N, K, npasses, relu);
    else
        gemm_mm<0><<<grid, 256, GEMM_SMEM>>>(A, B, C, bias, resid, N, K, npasses, relu);
}

static void run_attn(const float* qsrc, const float* kvsrc,
                     const float* W, const float* bias,
                     const float* sprev, float* sdst,
                     float* Q, float* K, float* V, float* O,
                     float* R, int* IDX, float* SW)
{
    run_gemm(qsrc,  W + 0*DD*DD, Q, bias + 0*DD, nullptr, DD, DD, 1, 0);
    run_gemm(kvsrc, W + 1*DD*DD, K, bias + 1*DD, nullptr, DD, DD, 1, 0);
    run_gemm(kvsrc, W + 2*DD*DD, V, bias + 2*DD, nullptr, DD, DD, 1, 0);
    zero_kernel<<<(BB*LL + 255)/256, 256>>>(R, BB*LL);
    dim3 cg(LL/BN, LL/BM, BB);
    corr_mm<<<cg, 256, GEMM_SMEM>>>(Q, K, R);
    topk_kernel<<<1, 256>>>(R, IDX, SW);
    agg_kernel<<<BLD/4/256, 256>>>(V, O, IDX, SW);
    run_gemm(O, W + 3*DD*DD, sdst, bias + 3*DD, sprev, DD, DD, 1, 0);
}

extern "C" void kernel_launch(void* const* d_in, const int* in_sizes, int n_in,
                              void* d_out, int out_size)
{
    const float* x_s      = (const float*)d_in[0];
    const float* x_w      = (const float*)d_in[1];
    const float* wc1_W    = (const float*)d_in[2];
    const float* wc1_b    = (const float*)d_in[3];
    const float* wc2_W    = (const float*)d_in[4];
    const float* wc2_b    = (const float*)d_in[5];
    const float* attn_W   = (const float*)d_in[6];
    const float* attn_b   = (const float*)d_in[7];
    const float* wc1_proj = (const float*)d_in[8];
    const float* wc2_proj = (const float*)d_in[9];
    const float* conv1_W  = (const float*)d_in[10];
    const float* conv2_W  = (const float*)d_in[11];

    float* out_res = (float*)d_out;
    float* out_w   = out_res + BLD;

    cudaFuncSetAttribute(gemm_mm<0>, cudaFuncAttributeMaxDynamicSharedMemorySize, GEMM_SMEM);
    cudaFuncSetAttribute(gemm_mm<1>, cudaFuncAttributeMaxDynamicSharedMemorySize, GEMM_SMEM);
    cudaFuncSetAttribute(corr_mm, cudaFuncAttributeMaxDynamicSharedMemorySize, GEMM_SMEM);

    float *Q, *K, *V, *O, *S, *T, *W1, *H, *R, *SW, *WT;
    int* IDX;
    cudaGetSymbolAddress((void**)&Q,   g_Q);
    cudaGetSymbolAddress((void**)&K,   g_K);
    cudaGetSymbolAddress((void**)&V,   g_V);
    cudaGetSymbolAddress((void**)&O,   g_O);
    cudaGetSymbolAddress((void**)&S,   g_S);
    cudaGetSymbolAddress((void**)&T,   g_T);
    cudaGetSymbolAddress((void**)&W1,  g_W1);
    cudaGetSymbolAddress((void**)&H,   g_H);
    cudaGetSymbolAddress((void**)&R,   g_R);
    cudaGetSymbolAddress((void**)&SW,  g_SW);
    cudaGetSymbolAddress((void**)&IDX, g_IDX);
    cudaGetSymbolAddress((void**)&WT,  g_WT);

    // 1) wc_decomp1: q=x_w, k=v=x_s;  S = x_s + attn(...)
    run_attn(x_w, x_s, wc1_W, wc1_b, x_s, S, Q, K, V, O, R, IDX, SW);

    // 2) W1 = token_embed(x_w, wc1_proj)  (3 register-accumulated shifted passes, 3xTF32)
    wtrans_kernel<<<3*DD*DD/256, 256>>>(wc1_proj, WT);
    run_gemm(x_w, WT, W1, nullptr, nullptr, DD, DD, 3, 0, 1);

    // 3) self-attention on S:  T = S + attn(S,S,S)
    run_attn(S, S, attn_W, attn_b, S, T, Q, K, V, O, R, IDX, SW);

    // 4) S = series_decomp(T)
    movavg_kernel<<<dim3(16, BB), 128>>>(T, S);

    // 5) wc_decomp2: q=W1, k=v=S;  T = S + attn(...)
    run_attn(W1, S, wc2_W, wc2_b, S, T, Q, K, V, O, R, IDX, SW);

    // 6) x_w_new = token_embed(W1, wc2_proj) -> second output (3xTF32)
    wtrans_kernel<<<3*DD*DD/256, 256>>>(wc2_proj, WT);
    run_gemm(W1, WT, out_w, nullptr, nullptr, DD, DD, 3, 0, 1);

    // 7) FFN: H = relu(T @ conv1_W^T); S = T + H @ conv2_W^T
    run_gemm(T, conv1_W, H, nullptr, nullptr, DFF, DD, 1, 1);
    run_gemm(H, conv2_W, S, nullptr, T, DD, DFF, 1, 0);

    // 8) res = series_decomp(S) -> first output
    movavg_kernel<<<dim3(16, BB), 128>>>(S, out_res);
}

// round 6
// speedup vs baseline: 4.8030x; 1.6893x over previous
#include <cuda_runtime.h>
#include <cuda_fp16.h>
#include <cstdint>
#include <cstddef>

#define BB  16
#define LL  1536
#define DD  512
#define DFF 2048
#define BLD (BB*LL*DD)

// tiles: 128x128 CTA, BK = 64 halves (128 bytes/row), 8 warps of 64x32
#define BM 128
#define BN 128
#define A_TILE 16384                    // 128 rows * 128 bytes
#define STAGE_BYTES (2*A_TILE)          // 32768
#define NSTAGE 3
#define GEMM_SMEM (NSTAGE*STAGE_BYTES)  // 98304
#define PR_STAGE (4*A_TILE)             // 65536 (Ahi|Alo|Bhi|Blo)
#define PR_SMEM (NSTAGE*PR_STAGE)       // 196608

// ---------------- device scratch ----------------
__device__ float  g_V[BLD];
__device__ float  g_O[BLD];
__device__ float  g_S[BLD];
__device__ float  g_T[BLD];
__device__ float  g_W1[BLD];
__device__ float  g_R[BB*LL];
__device__ float  g_SW[BB*8];
__device__ int    g_IDX[8];
__device__ float  g_WT[3*DD*DD];
__device__ __half g_hX[BLD];
__device__ __half g_hY[BLD];
__device__ __half g_hQ[BLD];
__device__ __half g_hK[BLD];
__device__ __half g_hH[(size_t)BB*LL*DFF];
__device__ __half g_hW[4*DD*DD];
__device__ __half g_hXhi[BLD];
__device__ __half g_hXlo[BLD];
__device__ __half g_hWhi[3*DD*DD];
__device__ __half g_hWlo[3*DD*DD];

// ---------------- PTX helpers ----------------
__device__ __forceinline__ uint32_t smem_u32(const void* p) {
    uint32_t a;
    asm("{ .reg .u64 t; cvta.to.shared.u64 t, %1; cvt.u32.u64 %0, t; }" : "=r"(a) : "l"(p));
    return a;
}
__device__ __forceinline__ void cp16(uint32_t s, const void* g) {
    asm volatile("cp.async.cg.shared.global [%0], [%1], 16;" :: "r"(s), "l"(g));
}
__device__ __forceinline__ void cp_commit() {
    asm volatile("cp.async.commit_group;" ::: "memory");
}
template<int N> __device__ __forceinline__ void cp_wait() {
    asm volatile("cp.async.wait_group %0;" :: "n"(N) : "memory");
}
__device__ __forceinline__ void mma_f16(float* d, const uint32_t* a, const uint32_t* b) {
    asm volatile("mma.sync.aligned.m16n8k16.row.col.f32.f16.f16.f32 "
        "{%0,%1,%2,%3}, {%4,%5,%6,%7}, {%8,%9}, {%0,%1,%2,%3};"
        : "+f"(d[0]), "+f"(d[1]), "+f"(d[2]), "+f"(d[3])
        : "r"(a[0]), "r"(a[1]), "r"(a[2]), "r"(a[3]), "r"(b[0]), "r"(b[1]));
}
__device__ __forceinline__ void ldsm4(uint32_t& r0, uint32_t& r1, uint32_t& r2, uint32_t& r3,
                                      uint32_t a) {
    asm volatile("ldmatrix.sync.aligned.m8n8.x4.shared.b16 {%0,%1,%2,%3}, [%4];"
        : "=r"(r0), "=r"(r1), "=r"(r2), "=r"(r3) : "r"(a));
}
__device__ __forceinline__ uint32_t swz16(uint32_t o) { return o ^ ((o >> 3) & 0x70); }

// =====================================================================
// fp16 HMMA GEMM: C[M,N] = A[M,K] @ B[N,K]^T (+bias)(+resid)(relu)
// OUTH=1: store half output. 3-stage cp.async, occ 2, ldmatrix.x4.
// =====================================================================
template<int OUTH>
__global__ __launch_bounds__(256, 2)
void gemm_mm(const __half* __restrict__ A, const __half* __restrict__ B,
             void* __restrict__ Cv, const float* __restrict__ bias,
             const float* __restrict__ resid, int N, int K, int relu)
{
    extern __shared__ char smem[];
    const uint32_t sb = smem_u32(smem);
    const int tid = threadIdx.x;
    const int lane = tid & 31, wid = tid >> 5;
    const int wr = wid & 1, wc = wid >> 1;
    const int m0 = blockIdx.y * BM, n0 = blockIdx.x * BN;
    const int T = K / 64;

    int arow[4], achk[4];
#pragma unroll
    for (int u = 0; u < 4; u++) { int q = tid*4 + u; arow[u] = q >> 3; achk[u] = q & 7; }

    auto load_stage = [&](int t) {
        int k0 = t * 64;
        uint32_t sA = sb + (t % NSTAGE) * STAGE_BYTES;
        uint32_t sB = sA + A_TILE;
#pragma unroll
        for (int u = 0; u < 4; u++)
            cp16(sA + swz16(arow[u]*128 + achk[u]*16),
                 A + (size_t)(m0 + arow[u]) * K + k0 + achk[u]*8);
#pragma unroll
        for (int u = 0; u < 4; u++)
            cp16(sB + swz16(arow[u]*128 + achk[u]*16),
                 B + (size_t)(n0 + arow[u]) * K + k0 + achk[u]*8);
        cp_commit();
    };

    load_stage(0); load_stage(1);

    float acc[4][4][4];
#pragma unroll
    for (int i = 0; i < 4; i++)
#pragma unroll
        for (int j = 0; j < 4; j++)
#pragma unroll
            for (int r = 0; r < 4; r++) acc[i][j][r] = 0.f;

    const int sw = lane & 7;
    int aoffs[4], boffs[2];
#pragma unroll
    for (int i = 0; i < 4; i++)
        aoffs[i] = (wr*64 + i*16 + ((lane >> 3) & 1)*8 + sw) * 128;
#pragma unroll
    for (int jp = 0; jp < 2; jp++)
        boffs[jp] = (wc*32 + jp*16 + ((lane >> 4) & 1)*8 + sw) * 128;
    const int aC = lane >> 4;
    const int bC = (lane >> 3) & 1;

    for (int t = 0; t < T; t++) {
        int rem = T - 1 - t;
        if (rem >= 1) cp_wait<1>(); else cp_wait<0>();
        __syncthreads();
        if (t + 2 < T) load_stage(t + 2);

        uint32_t sA = sb + (t % NSTAGE) * STAGE_BYTES;
        uint32_t sB = sA + A_TILE;
#pragma unroll
        for (int s16 = 0; s16 < 4; s16++) {
            uint32_t af[4][4], bf[4][2];
            uint32_t ach = (uint32_t)(((s16*2 + aC) ^ sw) << 4);
            uint32_t bch = (uint32_t)(((s16*2 + bC) ^ sw) << 4);
#pragma unroll
            for (int i = 0; i < 4; i++)
                ldsm4(af[i][0], af[i][1], af[i][2], af[i][3], sA + aoffs[i] + ach);
#pragma unroll
            for (int jp = 0; jp < 2; jp++)
                ldsm4(bf[2*jp][0], bf[2*jp][1], bf[2*jp+1][0], bf[2*jp+1][1],
                      sB + boffs[jp] + bch);
#pragma unroll
            for (int i = 0; i < 4; i++)
#pragma unroll
                for (int j = 0; j < 4; j++)
                    mma_f16(acc[i][j], af[i], bf[j]);
        }
    }

    // epilogue
#pragma unroll
    for (int i = 0; i < 4; i++) {
        int mrow = m0 + wr*64 + i*16 + (lane >> 2);
#pragma unroll
        for (int j = 0; j < 4; j++) {
            int n = n0 + wc*32 + j*8 + 2*(lane & 3);
#pragma unroll
            for (int h = 0; h < 2; h++) {
                int mm = mrow + h*8;
                float vx = acc[i][j][2*h+0], vy = acc[i][j][2*h+1];
                if (bias)  { vx += bias[n]; vy += bias[n+1]; }
                if (resid) {
                    float2 rv = *reinterpret_cast<const float2*>(&resid[(size_t)mm*N + n]);
                    vx += rv.x; vy += rv.y;
                }
                if (relu) { vx = fmaxf(vx, 0.f); vy = fmaxf(vy, 0.f); }
                if (OUTH) {
                    __half2 hv = __floats2half2_rn(vx, vy);
                    *reinterpret_cast<__half2*>(&((__half*)Cv)[(size_t)mm*N + n]) = hv;
                } else {
                    float2 v; v.x = vx; v.y = vy;
                    *reinterpret_cast<float2*>(&((float*)Cv)[(size_t)mm*N + n]) = v;
                }
            }
        }
    }
}

// =====================================================================
// fp16x3 precise GEMM (embeds): C = sum_pass (Ahi+Alo)(Bhi+Blo)^T, 3-term compensated.
// npasses: circular row shift by (pass-1) within each LL batch.
// =====================================================================
__global__ __launch_bounds__(256, 1)
void gemm_pr(const __half* __restrict__ Ahi, const __half* __restrict__ Alo,
             const __half* __restrict__ Bhi, const __half* __restrict__ Blo,
             float* __restrict__ C, int N, int K, int npasses)
{
    extern __shared__ char smem[];
    const uint32_t sb = smem_u32(smem);
    const int tid = threadIdx.x;
    const int lane = tid & 31, wid = tid >> 5;
    const int wr = wid & 1, wc = wid >> 1;
    const int m0 = blockIdx.y * BM, n0 = blockIdx.x * BN;
    const int kSteps = K / 64;
    const int T = npasses * kSteps;

    int arow[4], achk[4];
#pragma unroll
    for (int u = 0; u < 4; u++) { int q = tid*4 + u; arow[u] = q >> 3; achk[u] = q & 7; }

    auto load_stage = [&](int t) {
        int pass = t / kSteps;
        int k0 = (t - pass * kSteps) * 64;
        uint32_t s0 = sb + (t % NSTAGE) * PR_STAGE;
        const __half* Bh = Bhi + (size_t)pass * N * K;
        const __half* Bl = Blo + (size_t)pass * N * K;
#pragma unroll
        for (int u = 0; u < 4; u++) {
            int m = m0 + arow[u];
            int b = m / LL, l = m - b * LL;
            l += pass - 1;
            if (l < 0) l += LL; else if (l >= LL) l -= LL;
            size_t rg = (size_t)(b * LL + l) * K + k0 + achk[u]*8;
            uint32_t so = swz16(arow[u]*128 + achk[u]*16);
            cp16(s0 + so, Ahi + rg);
            cp16(s0 + A_TILE + so, Alo + rg);
            size_t bg = (size_t)(n0 + arow[u]) * K + k0 + achk[u]*8;
            cp16(s0 + 2*A_TILE + so, Bh + bg);
            cp16(s0 + 3*A_TILE + so, Bl + bg);
        }
        cp_commit();
    };

    load_stage(0); load_stage(1);

    float acc[4][4][4];
#pragma unroll
    for (int i = 0; i < 4; i++)
#pragma unroll
        for (int j = 0; j < 4; j++)
#pragma unroll
            for (int r = 0; r < 4; r++) acc[i][j][r] = 0.f;

    const int sw = lane & 7;
    int aoffs[4], boffs[2];
#pragma unroll
    for (int i = 0; i < 4; i++)
        aoffs[i] = (wr*64 + i*16 + ((lane >> 3) & 1)*8 + sw) * 128;
#pragma unroll
    for (int jp = 0; jp < 2; jp++)
        boffs[jp] = (wc*32 + jp*16 + ((lane >> 4) & 1)*8 + sw) * 128;
    const int aC = lane >> 4;
    const int bC = (lane >> 3) & 1;

    for (int t = 0; t < T; t++) {
        int rem = T - 1 - t;
        if (rem >= 1) cp_wait<1>(); else cp_wait<0>();
        __syncthreads();
        if (t + 2 < T) load_stage(t + 2);

        uint32_t s0 = sb + (t % NSTAGE) * PR_STAGE;
#pragma unroll
        for (int s16 = 0; s16 < 4; s16++) {
            uint32_t ah[4][4], al[4][4], bh[4][2], bl[4][2];
            uint32_t ach = (uint32_t)(((s16*2 + aC) ^ sw) << 4);
            uint32_t bch = (uint32_t)(((s16*2 + bC) ^ sw) << 4);
#pragma unroll
            for (int i = 0; i < 4; i++) {
                ldsm4(ah[i][0], ah[i][1], ah[i][2], ah[i][3], s0 + aoffs[i] + ach);
                ldsm4(al[i][0], al[i][1], al[i][2], al[i][3], s0 + A_TILE + aoffs[i] + ach);
            }
#pragma unroll
            for (int jp = 0; jp < 2; jp++) {
                ldsm4(bh[2*jp][0], bh[2*jp][1], bh[2*jp+1][0], bh[2*jp+1][1],
                      s0 + 2*A_TILE + boffs[jp] + bch);
                ldsm4(bl[2*jp][0], bl[2*jp][1], bl[2*jp+1][0], bl[2*jp+1][1],
                      s0 + 3*A_TILE + boffs[jp] + bch);
            }
#pragma unroll
            for (int i = 0; i < 4; i++)
#pragma unroll
                for (int j = 0; j < 4; j++) {
                    mma_f16(acc[i][j], al[i], bh[j]);
                    mma_f16(acc[i][j], ah[i], bl[j]);
                    mma_f16(acc[i][j], ah[i], bh[j]);
                }
        }
    }

#pragma unroll
    for (int i = 0; i < 4; i++) {
        int mrow = m0 + wr*64 + i*16 + (lane >> 2);
#pragma unroll
        for (int j = 0; j < 4; j++) {
            int n = n0 + wc*32 + j*8 + 2*(lane & 3);
#pragma unroll
            for (int h = 0; h < 2; h++) {
                int mm = mrow + h*8;
                float2 v; v.x = acc[i][j][2*h+0]; v.y = acc[i][j][2*h+1];
                *reinterpret_cast<float2*>(&C[(size_t)mm*N + n]) = v;
            }
        }
    }
}

// =====================================================================
// corr: r[b,tau] += diagonal sums of Q_b K_b^T over 128x128 tiles (fp16)
// =====================================================================
__global__ __launch_bounds__(256, 2)
void corr_mm(const __half* __restrict__ Q, const __half* __restrict__ Kb,
             float* __restrict__ r)
{
    extern __shared__ char smem[];
    const uint32_t sb = smem_u32(smem);
    const int tid = threadIdx.x;
    const int lane = tid & 31, wid = tid >> 5;
    const int wr = wid & 1, wc = wid >> 1;
    const int b = blockIdx.z;
    const int i0 = blockIdx.y * BM, j0 = blockIdx.x * BN;
    const __half* Qb = Q + (size_t)b * LL * DD;
    const __half* KB = Kb + (size_t)b * LL * DD;
    const int T = DD / 64;   // 8

    int arow[4], achk[4];
#pragma unroll
    for (int u = 0; u < 4; u++) { int q = tid*4 + u; arow[u] = q >> 3; achk[u] = q & 7; }

    auto load_stage = [&](int t) {
        int k0 = t * 64;
        uint32_t sA = sb + (t % NSTAGE) * STAGE_BYTES;
        uint32_t sB = sA + A_TILE;
#pragma unroll
        for (int u = 0; u < 4; u++)
            cp16(sA + swz16(arow[u]*128 + achk[u]*16),
                 Qb + (size_t)(i0 + arow[u]) * DD + k0 + achk[u]*8);
#pragma unroll
        for (int u = 0; u < 4; u++)
            cp16(sB + swz16(arow[u]*128 + achk[u]*16),
                 KB + (size_t)(j0 + arow[u]) * DD + k0 + achk[u]*8);
        cp_commit();
    };

    load_stage(0); load_stage(1);

    float acc[4][4][4];
#pragma unroll
    for (int i = 0; i < 4; i++)
#pragma unroll
        for (int j = 0; j < 4; j++)
#pragma unroll
            for (int q = 0; q < 4; q++) acc[i][j][q] = 0.f;

    const int sw = lane & 7;
    int aoffs[4], boffs[2];
#pragma unroll
    for (int i = 0; i < 4; i++)
        aoffs[i] = (wr*64 + i*16 + ((lane >> 3) & 1)*8 + sw) * 128;
#pragma unroll
    for (int jp = 0; jp < 2; jp++)
        boffs[jp] = (wc*32 + jp*16 + ((lane >> 4) & 1)*8 + sw) * 128;
    const int aC = lane >> 4;
    const int bC = (lane >> 3) & 1;

    for (int t = 0; t < T; t++) {
        int rem = T - 1 - t;
        if (rem >= 1) cp_wait<1>(); else cp_wait<0>();
        __syncthreads();
        if (t + 2 < T) load_stage(t + 2);

        uint32_t sA = sb + (t % NSTAGE) * STAGE_BYTES;
        uint32_t sB = sA + A_TILE;
#pragma unroll
        for (int s16 = 0; s16 < 4; s16++) {
            uint32_t af[4][4], bf[4][2];
            uint32_t ach = (uint32_t)(((s16*2 + aC) ^ sw) << 4);
            uint32_t bch = (uint32_t)(((s16*2 + bC) ^ sw) << 4);
#pragma unroll
            for (int i = 0; i < 4; i++)
                ldsm4(af[i][0], af[i][1], af[i][2], af[i][3], sA + aoffs[i] + ach);
#pragma unroll
            for (int jp = 0; jp < 2; jp++)
                ldsm4(bf[2*jp][0], bf[2*jp][1], bf[2*jp+1][0], bf[2*jp+1][1],
                      sB + boffs[jp] + bch);
#pragma unroll
            for (int i = 0; i < 4; i++)
#pragma unroll
                for (int j = 0; j < 4; j++)
                    mma_f16(acc[i][j], af[i], bf[j]);
        }
    }

    // spill tile to smem, diagonal-reduce, atomicAdd
    __syncthreads();
    float* Cs = (float*)smem;   // 128 x 130
#pragma unroll
    for (int i = 0; i < 4; i++) {
        int mrow = wr*64 + i*16 + (lane >> 2);
#pragma unroll
        for (int j = 0; j < 4; j++) {
            int n = wc*32 + j*8 + 2*(lane & 3);
#pragma unroll
            for (int h = 0; h < 2; h++) {
                float2 v; v.x = acc[i][j][2*h+0]; v.y = acc[i][j][2*h+1];
                *reinterpret_cast<float2*>(&Cs[(mrow + h*8)*130 + n]) = v;
            }
        }
    }
    __syncthreads();

    if (tid < 255) {
        int d = tid - 127;
        int ilo = d > 0 ? d : 0;
        int ihi = d < 0 ? 127 + d : 127;
        float s = 0.f;
        for (int i = ilo; i <= ihi; i++) s += Cs[i*130 + (i - d)];
        int tau = (i0 - j0 + d) % LL;
        if (tau < 0) tau += LL;
        atomicAdd(&r[(size_t)b * LL + tau], s);
    }
}

// ---------------- small kernels ----------------
__global__ void zero_kernel(float* p, int n)
{
    int i = blockIdx.x * 256 + threadIdx.x;
    if (i < n) p[i] = 0.f;
}

__global__ void cvt_h_kernel(const float* __restrict__ x, __half* __restrict__ y, int n4)
{
    int i = blockIdx.x * 256 + threadIdx.x;
    if (i < n4) {
        float4 v = reinterpret_cast<const float4*>(x)[i];
        __half2 h0 = __floats2half2_rn(v.x, v.y);
        __half2 h1 = __floats2half2_rn(v.z, v.w);
        reinterpret_cast<__half2*>(y)[2*i]   = h0;
        reinterpret_cast<__half2*>(y)[2*i+1] = h1;
    }
}

__global__ void cvt_split_kernel(const float* __restrict__ x,
                                 __half* __restrict__ hi, __half* __restrict__ lo, int n4)
{
    int i = blockIdx.x * 256 + threadIdx.x;
    if (i < n4) {
        float4 v = reinterpret_cast<const float4*>(x)[i];
        __half a = __float2half_rn(v.x), b2 = __float2half_rn(v.y);
        __half c = __float2half_rn(v.z), d = __float2half_rn(v.w);
        reinterpret_cast<__half2*>(hi)[2*i]   = __halves2half2(a, b2);
        reinterpret_cast<__half2*>(hi)[2*i+1] = __halves2half2(c, d);
        __half la = __float2half_rn(v.x - __half2float(a));
        __half lb = __float2half_rn(v.y - __half2float(b2));
        __half lc = __float2half_rn(v.z - __half2float(c));
        __half ld = __float2half_rn(v.w - __half2float(d));
        reinterpret_cast<__half2*>(lo)[2*i]   = __halves2half2(la, lb);
        reinterpret_cast<__half2*>(lo)[2*i+1] = __halves2half2(lc, ld);
    }
}

__global__ void wtrans_kernel(const float* __restrict__ Wp, float* __restrict__ Wt)
{
    int idx = blockIdx.x * 256 + threadIdx.x;   // 3*512*512
    int p = idx / (DD*DD);
    int rr = idx - p * (DD*DD);
    int n = rr >> 9, k = rr & 511;
    Wt[idx] = Wp[n * (DD*3) + k * 3 + p];
}

__global__ void topk_kernel(const float* __restrict__ r, int* __restrict__ gidx,
                            float* __restrict__ gsw)
{
    __shared__ float gv[LL];
    __shared__ float rv[256];
    __shared__ int   ri[256];
    __shared__ int   sidx[7];
    const int tid = threadIdx.x;

    for (int t = tid; t < LL; t += 256) {
        float s = 0.f;
        for (int b = 0; b < BB; b++) s += r[(size_t)b*LL + t];
        gv[t] = s;
    }
    __syncthreads();

    for (int it = 0; it < 7; it++) {
        float bv = -3.4e38f; int bi = 0;
        for (int t = tid; t < LL; t += 256) {
            float v = gv[t];
            if (v > bv) { bv = v; bi = t; }
        }
        rv[tid] = bv; ri[tid] = bi;
        __syncthreads();
        for (int s = 128; s > 0; s >>= 1) {
            if (tid < s) {
                if (rv[tid+s] > rv[tid] ||
                    (rv[tid+s] == rv[tid] && ri[tid+s] < ri[tid])) {
                    rv[tid] = rv[tid+s]; ri[tid] = ri[tid+s];
                }
            }
            __syncthreads();
        }
        if (tid == 0) { sidx[it] = ri[0]; gv[ri[0]] = -3.4e38f; }
        __syncthreads();
    }

    if (tid < 7) gidx[tid] = sidx[tid];
    if (tid < BB) {
        float w[7], m = -3.4e38f;
        for (int i = 0; i < 7; i++) {
            w[i] = r[(size_t)tid*LL + sidx[i]] * (1.0f / (float)DD);
            m = fmaxf(m, w[i]);
        }
        float sum = 0.f;
        for (int i = 0; i < 7; i++) { w[i] = expf(w[i] - m); sum += w[i]; }
        float inv = 1.0f / sum;
        for (int i = 0; i < 7; i++) gsw[tid*7 + i] = w[i] * inv;
    }
}

__global__ __launch_bounds__(256)
void agg_kernel(const float* __restrict__ V, float* __restrict__ O,
                const int* __restrict__ idxp, const float* __restrict__ swp)
{
    int g = blockIdx.x * 256 + threadIdx.x;
    int d4 = g & 127;
    int l  = (g >> 7) % LL;
    int b  = g / (LL * 128);

    int   idx[7];
    float w[7];
#pragma unroll
    for (int i = 0; i < 7; i++) { idx[i] = idxp[i]; w[i] = swp[b*7 + i]; }

    const float4* Vb = reinterpret_cast<const float4*>(V + (size_t)b * LL * DD);
    float4 acc = {0.f, 0.f, 0.f, 0.f};
#pragma unroll
    for (int i = 0; i < 7; i++) {
        int ls = l + idx[i];
        if (ls >= LL) ls -= LL;
        float4 v = Vb[(size_t)ls * 128 + d4];
        acc.x += w[i] * v.x; acc.y += w[i] * v.y;
        acc.z += w[i] * v.z; acc.w += w[i] * v.w;
    }
    reinterpret_cast<float4*>(O)[g] = acc;
}

__global__ __launch_bounds__(128)
void movavg_kernel(const float* __restrict__ X, float* __restrict__ out)
{
    const int b  = blockIdx.y;
    const int l0 = blockIdx.x * 96;
    const int d4 = threadIdx.x;
    const float4* x = reinterpret_cast<const float4*>(X + (size_t)b * LL * DD) + d4;
    float4* o = reinterpret_cast<float4*>(out + (size_t)b * LL * DD) + d4;

    float4 s = {0.f, 0.f, 0.f, 0.f};
    for (int j = -12; j <= 12; j++) {
        int lc = l0 + j;
        if (lc < 0) lc = 0;
        if (lc > LL-1) lc = LL-1;
        float4 v = x[(size_t)lc * 128];
        s.x += v.x; s.y += v.y; s.z += v.z; s.w += v.w;
    }
    const float inv = 1.0f / 25.0f;
    for (int t = 0; t < 96; t++) {
        int l = l0 + t;
        float4 xc = x[(size_t)l * 128];
        float4 rr;
        rr.x = xc.x - s.x * inv; rr.y = xc.y - s.y * inv;
        rr.z = xc.z - s.z * inv; rr.w = xc.w - s.w * inv;
        o[(size_t)l * 128] = rr;
        int la = l + 13; if (la > LL-1) la = LL-1;
        int lr = l - 12; if (lr < 0)    lr = 0;
        float4 va = x[(size_t)la * 128];
        float4 vr = x[(size_t)lr * 128];
        s.x += va.x - vr.x; s.y += va.y - vr.y;
        s.z += va.z - vr.z; s.w += va.w - vr.w;
    }
}

// ---------------- host orchestration ----------------
#define M_TOTAL (BB*LL)

static void cvt_h(const float* x, __half* y, size_t n)
{
    cvt_h_kernel<<<(int)((n/4 + 255)/256), 256>>>(x, y, (int)(n/4));
}
static void cvt_split(const float* x, __half* hi, __half* lo, size_t n)
{
    cvt_split_kernel<<<(int)((n/4 + 255)/256), 256>>>(x, hi, lo, (int)(n/4));
}
static void run_gemm(const __half* A, const __half* B, void* C,
                     const float* bias, const float* resid,
                     int N, int K, int relu, int outh)
{
    dim3 grid(N / BN, M_TOTAL / BM);
    if (outh)
        gemm_mm<1><<<grid, 256, GEMM_SMEM>>>(A, B, C, bias, resid, N, K, relu);
    else
        gemm_mm<0><<<grid, 256, GEMM_SMEM>>>(A, B, C, bias, resid, N, K, relu);
}

struct Ptrs {
    float *V, *O, *S, *T, *W1, *R, *SW, *WT;
    int* IDX;
    __half *hX, *hY, *hQ, *hK, *hH, *hW, *hXhi, *hXlo, *hWhi, *hWlo;
};

static void run_attn(const float* qsrc, const float* kvsrc,
                     const float* W, const float* bias,
                     const float* sprev, float* sdst, const Ptrs& p)
{
    cvt_h(qsrc, p.hX, BLD);
    const __half* hYp = p.hX;
    if (kvsrc != qsrc) { cvt_h(kvsrc, p.hY, BLD); hYp = p.hY; }
    cvt_h(W, p.hW, (size_t)4*DD*DD);

    run_gemm(p.hX, p.hW + 0*DD*DD, p.hQ, bias + 0*DD, nullptr, DD, DD, 0, 1);
    run_gemm(hYp,  p.hW + 1*DD*DD, p.hK, bias + 1*DD, nullptr, DD, DD, 0, 1);
    run_gemm(hYp,  p.hW + 2*DD*DD, p.V,  bias + 2*DD, nullptr, DD, DD, 0, 0);

    zero_kernel<<<(BB*LL + 255)/256, 256>>>(p.R, BB*LL);
    dim3 cg(LL/BN, LL/BM, BB);
    corr_mm<<<cg, 256, GEMM_SMEM>>>(p.hQ, p.hK, p.R);
    topk_kernel<<<1, 256>>>(p.R, p.IDX, p.SW);
    agg_kernel<<<BLD/4/256, 256>>>(p.V, p.O, p.IDX, p.SW);

    cvt_h(p.O, p.hX, BLD);
    run_gemm(p.hX, p.hW + 3*DD*DD, sdst, bias + 3*DD, sprev, DD, DD, 0, 0);
}

static void run_embed(const float* src, const float* proj, float* dst, const Ptrs& p)
{
    wtrans_kernel<<<3*DD*DD/256, 256>>>(proj, p.WT);
    cvt_split(p.WT, p.hWhi, p.hWlo, (size_t)3*DD*DD);
    cvt_split(src, p.hXhi, p.hXlo, BLD);
    dim3 grid(DD / BN, M_TOTAL / BM);
    gemm_pr<<<grid, 256, PR_SMEM>>>(p.hXhi, p.hXlo, p.hWhi, p.hWlo, dst, DD, DD, 3);
}

extern "C" void kernel_launch(void* const* d_in, const int* in_sizes, int n_in,
                              void* d_out, int out_size)
{
    const float* x_s      = (const float*)d_in[0];
    const float* x_w      = (const float*)d_in[1];
    const float* wc1_W    = (const float*)d_in[2];
    const float* wc1_b    = (const float*)d_in[3];
    const float* wc2_W    = (const float*)d_in[4];
    const float* wc2_b    = (const float*)d_in[5];
    const float* attn_W   = (const float*)d_in[6];
    const float* attn_b   = (const float*)d_in[7];
    const float* wc1_proj = (const float*)d_in[8];
    const float* wc2_proj = (const float*)d_in[9];
    const float* conv1_W  = (const float*)d_in[10];
    const float* conv2_W  = (const float*)d_in[11];

    float* out_res = (float*)d_out;
    float* out_w   = out_res + BLD;

    cudaFuncSetAttribute(gemm_mm<0>, cudaFuncAttributeMaxDynamicSharedMemorySize, GEMM_SMEM);
    cudaFuncSetAttribute(gemm_mm<1>, cudaFuncAttributeMaxDynamicSharedMemorySize, GEMM_SMEM);
    cudaFuncSetAttribute(corr_mm,    cudaFuncAttributeMaxDynamicSharedMemorySize, GEMM_SMEM);
    cudaFuncSetAttribute(gemm_pr,    cudaFuncAttributeMaxDynamicSharedMemorySize, PR_SMEM);

    Ptrs p;
    cudaGetSymbolAddress((void**)&p.V,    g_V);
    cudaGetSymbolAddress((void**)&p.O,    g_O);
    cudaGetSymbolAddress((void**)&p.S,    g_S);
    cudaGetSymbolAddress((void**)&p.T,    g_T);
    cudaGetSymbolAddress((void**)&p.W1,   g_W1);
    cudaGetSymbolAddress((void**)&p.R,    g_R);
    cudaGetSymbolAddress((void**)&p.SW,   g_SW);
    cudaGetSymbolAddress((void**)&p.WT,   g_WT);
    cudaGetSymbolAddress((void**)&p.IDX,  g_IDX);
    cudaGetSymbolAddress((void**)&p.hX,   g_hX);
    cudaGetSymbolAddress((void**)&p.hY,   g_hY);
    cudaGetSymbolAddress((void**)&p.hQ,   g_hQ);
    cudaGetSymbolAddress((void**)&p.hK,   g_hK);
    cudaGetSymbolAddress((void**)&p.hH,   g_hH);
    cudaGetSymbolAddress((void**)&p.hW,   g_hW);
    cudaGetSymbolAddress((void**)&p.hXhi, g_hXhi);
    cudaGetSymbolAddress((void**)&p.hXlo, g_hXlo);
    cudaGetSymbolAddress((void**)&p.hWhi, g_hWhi);
    cudaGetSymbolAddress((void**)&p.hWlo, g_hWlo);

    // 1) wc_decomp1: q=x_w, k=v=x_s;  S = x_s + attn(...)
    run_attn(x_w, x_s, wc1_W, wc1_b, x_s, p.S, p);

    // 2) W1 = token_embed(x_w, wc1_proj)  (fp16x3, 3 shifted passes)
    run_embed(x_w, wc1_proj, p.W1, p);

    // 3) self-attention on S:  T = S + attn(S,S,S)
    run_attn(p.S, p.S, attn_W, attn_b, p.S, p.T, p);

    // 4) S = series_decomp(T)
    movavg_kernel<<<dim3(16, BB), 128>>>(p.T, p.S);

    // 5) wc_decomp2: q=W1, k=v=S;  T = S + attn(...)
    run_attn(p.W1, p.S, wc2_W, wc2_b, p.S, p.T, p);

    // 6) x_w_new = token_embed(W1, wc2_proj) -> second output
    run_embed(p.W1, wc2_proj, out_w, p);

    // 7) FFN: H = relu(T @ conv1_W^T) (half out); S = T + H @ conv2_W^T
    cvt_h(p.T, p.hX, BLD);
    cvt_h(conv1_W, p.hW, (size_t)DFF*DD);
    run_gemm(p.hX, p.hW, p.hH, nullptr, nullptr, DFF, DD, 1, 1);
    cvt_h(conv2_W, p.hW, (size_t)DD*DFF);
    run_gemm(p.hH, p.hW, p.S, nullptr, p.T, DD, DFF, 0, 0);

    // 8) res = series_decomp(S) -> first output
    movavg_kernel<<<dim3(16, BB), 128>>>(p.S, out_res);
}

// round 11
// speedup vs baseline: 6.0576x; 1.2612x over previous
#include <cuda_runtime.h>
#include <cuda_fp16.h>
#include <cstdint>
#include <cstddef>

#define BB  16
#define LL  1536
#define DD  512
#define DFF 2048
#define BLD (BB*LL*DD)
#define M_TOTAL (BB*LL)

// tiles: 128x128 CTA, BK = 64 halves (128 bytes/row), 8 warps of 64x32
#define BM 128
#define BN 128
#define A_TILE 16384
#define STAGE_BYTES (2*A_TILE)
#define NSTAGE 3
#define GEMM_SMEM (NSTAGE*STAGE_BYTES)  // 98304

// ---------------- device scratch ----------------
__device__ float  g_S[BLD];
__device__ float  g_T[BLD];
__device__ float  g_R[BB*LL];
__device__ float  g_SW[BB*8];
__device__ int    g_IDX[8];
__device__ __half g_hXS[BLD];
__device__ __half g_hXW[BLD];
__device__ __half g_hQ[BLD];
__device__ __half g_hK[BLD];
__device__ __half g_hV[BLD];
__device__ __half g_hS[BLD];
__device__ __half g_hO[BLD];
__device__ __half g_hW1[BLD];
__device__ __half g_hT[BLD];
__device__ __half g_hH[(size_t)BB*LL*DFF];
__device__ __half g_hW[4*DD*DD];
__device__ __half g_hWT[3*DD*DD];

// ---------------- PTX helpers ----------------
__device__ __forceinline__ uint32_t smem_u32(const void* p) {
    uint32_t a;
    asm("{ .reg .u64 t; cvta.to.shared.u64 t, %1; cvt.u32.u64 %0, t; }" : "=r"(a) : "l"(p));
    return a;
}
__device__ __forceinline__ void cp16(uint32_t s, const void* g) {
    asm volatile("cp.async.cg.shared.global [%0], [%1], 16;" :: "r"(s), "l"(g));
}
__device__ __forceinline__ void cp_commit() {
    asm volatile("cp.async.commit_group;" ::: "memory");
}
template<int N> __device__ __forceinline__ void cp_wait() {
    asm volatile("cp.async.wait_group %0;" :: "n"(N) : "memory");
}
__device__ __forceinline__ void mma_f16(float* d, const uint32_t* a, const uint32_t* b) {
    asm volatile("mma.sync.aligned.m16n8k16.row.col.f32.f16.f16.f32 "
        "{%0,%1,%2,%3}, {%4,%5,%6,%7}, {%8,%9}, {%0,%1,%2,%3};"
        : "+f"(d[0]), "+f"(d[1]), "+f"(d[2]), "+f"(d[3])
        : "r"(a[0]), "r"(a[1]), "r"(a[2]), "r"(a[3]), "r"(b[0]), "r"(b[1]));
}
__device__ __forceinline__ void ldsm4(uint32_t& r0, uint32_t& r1, uint32_t& r2, uint32_t& r3,
                                      uint32_t a) {
    asm volatile("ldmatrix.sync.aligned.m8n8.x4.shared.b16 {%0,%1,%2,%3}, [%4];"
        : "=r"(r0), "=r"(r1), "=r"(r2), "=r"(r3) : "r"(a));
}
__device__ __forceinline__ uint32_t swz16(uint32_t o) { return o ^ ((o >> 3) & 0x70); }

// =====================================================================
// fp16 HMMA GEMM: C = sum_pass A_pass[M,K] @ B_pass[N,K]^T (+bias)(+resid f32)(relu)
// MODE 0: f32 out (Cf).  MODE 1: half out (Ch0, stride N).
// MODE 2: dual f32 (Cf) + half (Ch0).  MODE 3: split half dsts per 512 cols.
// npasses>1: embed conv; pass p shifts A rows circularly by (p-1) within each LL batch.
// =====================================================================
template<int MODE>
__global__ __launch_bounds__(256, 2)
void gemm_mm(const __half* __restrict__ A, const __half* __restrict__ B,
             float* __restrict__ Cf, __half* __restrict__ Ch0,
             __half* __restrict__ Ch1, __half* __restrict__ Ch2,
             const float* __restrict__ bias, const float* __restrict__ resid,
             int N, int K, int npasses, int relu)
{
    extern __shared__ char smem[];
    const uint32_t sb = smem_u32(smem);
    const int tid = threadIdx.x;
    const int lane = tid & 31, wid = tid >> 5;
    const int wr = wid & 1, wc = wid >> 1;
    const int m0 = blockIdx.y * BM, n0 = blockIdx.x * BN;
    const int kSteps = K / 64;
    const int T = npasses * kSteps;

    int arow[4], achk[4];
#pragma unroll
    for (int u = 0; u < 4; u++) { int q = tid*4 + u; arow[u] = q >> 3; achk[u] = q & 7; }

    auto load_stage = [&](int t) {
        int pass = (npasses > 1) ? (t / kSteps) : 0;
        int k0 = (t - pass * kSteps) * 64;
        uint32_t sA = sb + (t % NSTAGE) * STAGE_BYTES;
        uint32_t sB = sA + A_TILE;
        const __half* Bp = B + (size_t)pass * N * K;
#pragma unroll
        for (int u = 0; u < 4; u++) {
            int m = m0 + arow[u], rg = m;
            if (npasses > 1) {
                int b = m / LL, l = m - b * LL;
                l += pass - 1;
                if (l < 0) l += LL; else if (l >= LL) l -= LL;
                rg = b * LL + l;
            }
            cp16(sA + swz16(arow[u]*128 + achk[u]*16),
                 A + (size_t)rg * K + k0 + achk[u]*8);
        }
#pragma unroll
        for (int u = 0; u < 4; u++)
            cp16(sB + swz16(arow[u]*128 + achk[u]*16),
                 Bp + (size_t)(n0 + arow[u]) * K + k0 + achk[u]*8);
        cp_commit();
    };

    load_stage(0); load_stage(1);

    float acc[4][4][4];
#pragma unroll
    for (int i = 0; i < 4; i++)
#pragma unroll
        for (int j = 0; j < 4; j++)
#pragma unroll
            for (int r = 0; r < 4; r++) acc[i][j][r] = 0.f;

    const int sw = lane & 7;
    int aoffs[4], boffs[2];
#pragma unroll
    for (int i = 0; i < 4; i++)
        aoffs[i] = (wr*64 + i*16 + ((lane >> 3) & 1)*8 + sw) * 128;
#pragma unroll
    for (int jp = 0; jp < 2; jp++)
        boffs[jp] = (wc*32 + jp*16 + ((lane >> 4) & 1)*8 + sw) * 128;
    const int aC = lane >> 4;
    const int bC = (lane >> 3) & 1;

    for (int t = 0; t < T; t++) {
        int rem = T - 1 - t;
        if (rem >= 1) cp_wait<1>(); else cp_wait<0>();
        __syncthreads();
        if (t + 2 < T) load_stage(t + 2);

        uint32_t sA = sb + (t % NSTAGE) * STAGE_BYTES;
        uint32_t sB = sA + A_TILE;
#pragma unroll
        for (int s16 = 0; s16 < 4; s16++) {
            uint32_t af[4][4], bf[4][2];
            uint32_t ach = (uint32_t)(((s16*2 + aC) ^ sw) << 4);
            uint32_t bch = (uint32_t)(((s16*2 + bC) ^ sw) << 4);
#pragma unroll
            for (int i = 0; i < 4; i++)
                ldsm4(af[i][0], af[i][1], af[i][2], af[i][3], sA + aoffs[i] + ach);
#pragma unroll
            for (int jp = 0; jp < 2; jp++)
                ldsm4(bf[2*jp][0], bf[2*jp][1], bf[2*jp+1][0], bf[2*jp+1][1],
                      sB + boffs[jp] + bch);
#pragma unroll
            for (int i = 0; i < 4; i++)
#pragma unroll
                for (int j = 0; j < 4; j++)
                    mma_f16(acc[i][j], af[i], bf[j]);
        }
    }

    // epilogue
#pragma unroll
    for (int i = 0; i < 4; i++) {
        int mrow = m0 + wr*64 + i*16 + (lane >> 2);
#pragma unroll
        for (int j = 0; j < 4; j++) {
            int n = n0 + wc*32 + j*8 + 2*(lane & 3);
#pragma unroll
            for (int h = 0; h < 2; h++) {
                int mm = mrow + h*8;
                float vx = acc[i][j][2*h+0], vy = acc[i][j][2*h+1];
                if (bias)  { vx += bias[n]; vy += bias[n+1]; }
                if (resid) {
                    float2 rv = *reinterpret_cast<const float2*>(&resid[(size_t)mm*N + n]);
                    vx += rv.x; vy += rv.y;
                }
                if (relu) { vx = fmaxf(vx, 0.f); vy = fmaxf(vy, 0.f); }
                if (MODE == 0 || MODE == 2) {
                    float2 v; v.x = vx; v.y = vy;
                    *reinterpret_cast<float2*>(&Cf[(size_t)mm*N + n]) = v;
                }
                if (MODE == 1 || MODE == 2) {
                    __half2 hv = __floats2half2_rn(vx, vy);
                    *reinterpret_cast<__half2*>(&Ch0[(size_t)mm*N + n]) = hv;
                }
                if (MODE == 3) {
                    __half* dst = (n < 512) ? Ch0 : ((n < 1024) ? Ch1 : Ch2);
                    int col = n & 511;
                    __half2 hv = __floats2half2_rn(vx, vy);
                    *reinterpret_cast<__half2*>(&dst[(size_t)mm*512 + col]) = hv;
                }
            }
        }
    }
}

// =====================================================================
// corr: r[b,tau] += diagonal sums of Q_b K_b^T over 128x128 tiles (fp16)
// =====================================================================
__global__ __launch_bounds__(256, 2)
void corr_mm(const __half* __restrict__ Q, const __half* __restrict__ Kb,
             float* __restrict__ r)
{
    extern __shared__ char smem[];
    const uint32_t sb = smem_u32(smem);
    const int tid = threadIdx.x;
    const int lane = tid & 31, wid = tid >> 5;
    const int wr = wid & 1, wc = wid >> 1;
    const int b = blockIdx.z;
    const int i0 = blockIdx.y * BM, j0 = blockIdx.x * BN;
    const __half* Qb = Q + (size_t)b * LL * DD;
    const __half* KB = Kb + (size_t)b * LL * DD;
    const int T = DD / 64;   // 8

    int arow[4], achk[4];
#pragma unroll
    for (int u = 0; u < 4; u++) { int q = tid*4 + u; arow[u] = q >> 3; achk[u] = q & 7; }

    auto load_stage = [&](int t) {
        int k0 = t * 64;
        uint32_t sA = sb + (t % NSTAGE) * STAGE_BYTES;
        uint32_t sB = sA + A_TILE;
#pragma unroll
        for (int u = 0; u < 4; u++)
            cp16(sA + swz16(arow[u]*128 + achk[u]*16),
                 Qb + (size_t)(i0 + arow[u]) * DD + k0 + achk[u]*8);
#pragma unroll
        for (int u = 0; u < 4; u++)
            cp16(sB + swz16(arow[u]*128 + achk[u]*16),
                 KB + (size_t)(j0 + arow[u]) * DD + k0 + achk[u]*8);
        cp_commit();
    };

    load_stage(0); load_stage(1);

    float acc[4][4][4];
#pragma unroll
    for (int i = 0; i < 4; i++)
#pragma unroll
        for (int j = 0; j < 4; j++)
#pragma unroll
            for (int q = 0; q < 4; q++) acc[i][j][q] = 0.f;

    const int sw = lane & 7;
    int aoffs[4], boffs[2];
#pragma unroll
    for (int i = 0; i < 4; i++)
        aoffs[i] = (wr*64 + i*16 + ((lane >> 3) & 1)*8 + sw) * 128;
#pragma unroll
    for (int jp = 0; jp < 2; jp++)
        boffs[jp] = (wc*32 + jp*16 + ((lane >> 4) & 1)*8 + sw) * 128;
    const int aC = lane >> 4;
    const int bC = (lane >> 3) & 1;

    for (int t = 0; t < T; t++) {
        int rem = T - 1 - t;
        if (rem >= 1) cp_wait<1>(); else cp_wait<0>();
        __syncthreads();
        if (t + 2 < T) load_stage(t + 2);

        uint32_t sA = sb + (t % NSTAGE) * STAGE_BYTES;
        uint32_t sB = sA + A_TILE;
#pragma unroll
        for (int s16 = 0; s16 < 4; s16++) {
            uint32_t af[4][4], bf[4][2];
            uint32_t ach = (uint32_t)(((s16*2 + aC) ^ sw) << 4);
            uint32_t bch = (uint32_t)(((s16*2 + bC) ^ sw) << 4);
#pragma unroll
            for (int i = 0; i < 4; i++)
                ldsm4(af[i][0], af[i][1], af[i][2], af[i][3], sA + aoffs[i] + ach);
#pragma unroll
            for (int jp = 0; jp < 2; jp++)
                ldsm4(bf[2*jp][0], bf[2*jp][1], bf[2*jp+1][0], bf[2*jp+1][1],
                      sB + boffs[jp] + bch);
#pragma unroll
            for (int i = 0; i < 4; i++)
#pragma unroll
                for (int j = 0; j < 4; j++)
                    mma_f16(acc[i][j], af[i], bf[j]);
        }
    }

    __syncthreads();
    float* Cs = (float*)smem;   // 128 x 130
#pragma unroll
    for (int i = 0; i < 4; i++) {
        int mrow = wr*64 + i*16 + (lane >> 2);
#pragma unroll
        for (int j = 0; j < 4; j++) {
            int n = wc*32 + j*8 + 2*(lane & 3);
#pragma unroll
            for (int h = 0; h < 2; h++) {
                float2 v; v.x = acc[i][j][2*h+0]; v.y = acc[i][j][2*h+1];
                *reinterpret_cast<float2*>(&Cs[(mrow + h*8)*130 + n]) = v;
            }
        }
    }
    __syncthreads();

    if (tid < 255) {
        int d = tid - 127;
        int ilo = d > 0 ? d : 0;
        int ihi = d < 0 ? 127 + d : 127;
        float s = 0.f;
        for (int i = ilo; i <= ihi; i++) s += Cs[i*130 + (i - d)];
        int tau = (i0 - j0 + d) % LL;
        if (tau < 0) tau += LL;
        atomicAdd(&r[(size_t)b * LL + tau], s);
    }
}

// ---------------- small kernels ----------------
__global__ void zero_kernel(float* p, int n)
{
    int i = blockIdx.x * 256 + threadIdx.x;
    if (i < n) p[i] = 0.f;
}

__global__ void cvt_h_kernel(const float* __restrict__ x, __half* __restrict__ y, int n4)
{
    int i = blockIdx.x * 256 + threadIdx.x;
    if (i < n4) {
        float4 v = reinterpret_cast<const float4*>(x)[i];
        reinterpret_cast<__half2*>(y)[2*i]   = __floats2half2_rn(v.x, v.y);
        reinterpret_cast<__half2*>(y)[2*i+1] = __floats2half2_rn(v.z, v.w);
    }
}

// W[n, k*3+p] (f32) -> Wt[p][n][k] (half, K-major per pass)
__global__ void wtrans_h_kernel(const float* __restrict__ Wp, __half* __restrict__ Wt)
{
    int idx = blockIdx.x * 256 + threadIdx.x;   // 3*512*512
    int p = idx / (DD*DD);
    int rr = idx - p * (DD*DD);
    int n = rr >> 9, k = rr & 511;
    Wt[idx] = __float2half_rn(Wp[n * (DD*3) + k * 3 + p]);
}

__global__ void topk_kernel(const float* __restrict__ r, int* __restrict__ gidx,
                            float* __restrict__ gsw)
{
    __shared__ float gv[LL];
    __shared__ float rv[256];
    __shared__ int   ri[256];
    __shared__ int   sidx[7];
    const int tid = threadIdx.x;

    for (int t = tid; t < LL; t += 256) {
        float s = 0.f;
        for (int b = 0; b < BB; b++) s += r[(size_t)b*LL + t];
        gv[t] = s;
    }
    __syncthreads();

    for (int it = 0; it < 7; it++) {
        float bv = -3.4e38f; int bi = 0;
        for (int t = tid; t < LL; t += 256) {
            float v = gv[t];
            if (v > bv) { bv = v; bi = t; }
        }
        rv[tid] = bv; ri[tid] = bi;
        __syncthreads();
        for (int s = 128; s > 0; s >>= 1) {
            if (tid < s) {
                if (rv[tid+s] > rv[tid] ||
                    (rv[tid+s] == rv[tid] && ri[tid+s] < ri[tid])) {
                    rv[tid] = rv[tid+s]; ri[tid] = ri[tid+s];
                }
            }
            __syncthreads();
        }
        if (tid == 0) { sidx[it] = ri[0]; gv[ri[0]] = -3.4e38f; }
        __syncthreads();
    }

    if (tid < 7) gidx[tid] = sidx[tid];
    if (tid < BB) {
        float w[7], m = -3.4e38f;
        for (int i = 0; i < 7; i++) {
            w[i] = r[(size_t)tid*LL + sidx[i]] * (1.0f / (float)DD);
            m = fmaxf(m, w[i]);
        }
        float sum = 0.f;
        for (int i = 0; i < 7; i++) { w[i] = expf(w[i] - m); sum += w[i]; }
        float inv = 1.0f / sum;
        for (int i = 0; i < 7; i++) gsw[tid*7 + i] = w[i] * inv;
    }
}

// aggregation in half: O[b,l,:] = sum_i w[b,i]*V[b,(l+idx[i])%L,:]
__global__ __launch_bounds__(256)
void agg_h_kernel(const __half* __restrict__ V, __half* __restrict__ O,
                  const int* __restrict__ idxp, const float* __restrict__ swp)
{
    int g = blockIdx.x * 256 + threadIdx.x;     // over BLD/8
    int d8 = g & 63;
    int l  = (g >> 6) % LL;
    int b  = g / (LL * 64);

    int   idx[7];
    float w[7];
#pragma unroll
    for (int i = 0; i < 7; i++) { idx[i] = idxp[i]; w[i] = swp[b*7 + i]; }

    const uint4* Vb = reinterpret_cast<const uint4*>(V + (size_t)b * LL * DD);
    float acc[8];
#pragma unroll
    for (int q = 0; q < 8; q++) acc[q] = 0.f;
#pragma unroll
    for (int i = 0; i < 7; i++) {
        int ls = l + idx[i];
        if (ls >= LL) ls -= LL;
        uint4 v = Vb[(size_t)ls * 64 + d8];
        const __half2* hp = reinterpret_cast<const __half2*>(&v);
#pragma unroll
        for (int q = 0; q < 4; q++) {
            float2 f = __half22float2(hp[q]);
            acc[2*q+0] += w[i] * f.x;
            acc[2*q+1] += w[i] * f.y;
        }
    }
    uint4 out;
    __half2* op = reinterpret_cast<__half2*>(&out);
#pragma unroll
    for (int q = 0; q < 4; q++) op[q] = __floats2half2_rn(acc[2*q], acc[2*q+1]);
    reinterpret_cast<uint4*>(O)[g] = out;
}

// series_decomp with optional half mirror output
__global__ __launch_bounds__(128)
void movavg_kernel(const float* __restrict__ X, float* __restrict__ out,
                   __half* __restrict__ outh)
{
    const int b  = blockIdx.y;
    const int l0 = blockIdx.x * 96;
    const int d4 = threadIdx.x;
    const float4* x = reinterpret_cast<const float4*>(X + (size_t)b * LL * DD) + d4;
    float4* o = reinterpret_cast<float4*>(out + (size_t)b * LL * DD) + d4;
    __half2* oh = outh ? (reinterpret_cast<__half2*>(outh + (size_t)b * LL * DD) + d4*2)
                       : (__half2*)nullptr;

    float4 s = {0.f, 0.f, 0.f, 0.f};
    for (int j = -12; j <= 12; j++) {
        int lc = l0 + j;
        if (lc < 0) lc = 0;
        if (lc > LL-1) lc = LL-1;
        float4 v = x[(size_t)lc * 128];
        s.x += v.x; s.y += v.y; s.z += v.z; s.w += v.w;
    }
    const float inv = 1.0f / 25.0f;
    for (int t = 0; t < 96; t++) {
        int l = l0 + t;
        float4 xc = x[(size_t)l * 128];
        float4 rr;
        rr.x = xc.x - s.x * inv; rr.y = xc.y - s.y * inv;
        rr.z = xc.z - s.z * inv; rr.w = xc.w - s.w * inv;
        o[(size_t)l * 128] = rr;
        if (outh) {
            oh[(size_t)l * 256]     = __floats2half2_rn(rr.x, rr.y);
            oh[(size_t)l * 256 + 1] = __floats2half2_rn(rr.z, rr.w);
        }
        int la = l + 13; if (la > LL-1) la = LL-1;
        int lr = l - 12; if (lr < 0)    lr = 0;
        float4 va = x[(size_t)la * 128];
        float4 vr = x[(size_t)lr * 128];
        s.x += va.x - vr.x; s.y += va.y - vr.y;
        s.z += va.z - vr.z; s.w += va.w - vr.w;
    }
}

// ---------------- host orchestration ----------------
static void cvt_h(const float* x, __half* y, size_t n)
{
    cvt_h_kernel<<<(int)((n/4 + 255)/256), 256>>>(x, y, (int)(n/4));
}

static void launch_gemm(int mode, const __half* A, const __half* B,
                        float* Cf, __half* h0, __half* h1, __half* h2,
                        const float* bias, const float* resid,
                        int N, int K, int npasses, int relu)
{
    dim3 grid(N / BN, M_TOTAL / BM);
    switch (mode) {
    case 0: gemm_mm<0><<<grid, 256, GEMM_SMEM>>>(A,B,Cf,h0,h1,h2,bias,resid,N,K,npasses,relu); break;
    case 1: gemm_mm<1><<<grid, 256, GEMM_SMEM>>>(A,B,Cf,h0,h1,h2,bias,resid,N,K,npasses,relu); break;
    case 2: gemm_mm<2><<<grid, 256, GEMM_SMEM>>>(A,B,Cf,h0,h1,h2,bias,resid,N,K,npasses,relu); break;
    default: gemm_mm<3><<<grid, 256, GEMM_SMEM>>>(A,B,Cf,h0,h1,h2,bias,resid,N,K,npasses,relu); break;
    }
}

struct Ptrs {
    float *S, *T, *R, *SW;
    int* IDX;
    __half *hXS, *hXW, *hQ, *hK, *hV, *hS, *hO, *hW1, *hT, *hH, *hW, *hWT;
};

// attention block: Cf = resid + attn(hq, hkv, hkv); optional half mirror Ch
static void run_attn(const __half* hq, const __half* hkv,
                     const float* W, const float* bias,
                     const float* resid, float* Cf, __half* Ch, const Ptrs& p)
{
    cvt_h(W, p.hW, (size_t)4*DD*DD);
    if (hq == hkv) {
        launch_gemm(3, hq, p.hW, nullptr, p.hQ, p.hK, p.hV, bias, nullptr, 3*DD, DD, 1, 0);
    } else {
        launch_gemm(1, hq,  p.hW, nullptr, p.hQ, nullptr, nullptr, bias, nullptr, DD, DD, 1, 0);
        launch_gemm(3, hkv, p.hW + DD*DD, nullptr, p.hK, p.hV, nullptr, bias + DD, nullptr,
                    2*DD, DD, 1, 0);
    }
    zero_kernel<<<(BB*LL + 255)/256, 256>>>(p.R, BB*LL);
    dim3 cg(LL/BN, LL/BM, BB);
    corr_mm<<<cg, 256, GEMM_SMEM>>>(p.hQ, p.hK, p.R);
    topk_kernel<<<1, 256>>>(p.R, p.IDX, p.SW);
    agg_h_kernel<<<BLD/8/256, 256>>>(p.hV, p.hO, p.IDX, p.SW);
    launch_gemm(Ch ? 2 : 0, p.hO, p.hW + 3*DD*DD, Cf, Ch, nullptr, nullptr,
                bias + 3*DD, resid, DD, DD, 1, 0);
}

extern "C" void kernel_launch(void* const* d_in, const int* in_sizes, int n_in,
                              void* d_out, int out_size)
{
    const float* x_s      = (const float*)d_in[0];
    const float* x_w      = (const float*)d_in[1];
    const float* wc1_W    = (const float*)d_in[2];
    const float* wc1_b    = (const float*)d_in[3];
    const float* wc2_W    = (const float*)d_in[4];
    const float* wc2_b    = (const float*)d_in[5];
    const float* attn_W   = (const float*)d_in[6];
    const float* attn_b   = (const float*)d_in[7];
    const float* wc1_proj = (const float*)d_in[8];
    const float* wc2_proj = (const float*)d_in[9];
    const float* conv1_W  = (const float*)d_in[10];
    const float* conv2_W  = (const float*)d_in[11];

    float* out_res = (float*)d_out;
    float* out_w   = out_res + BLD;

    cudaFuncSetAttribute(gemm_mm<0>, cudaFuncAttributeMaxDynamicSharedMemorySize, GEMM_SMEM);
    cudaFuncSetAttribute(gemm_mm<1>, cudaFuncAttributeMaxDynamicSharedMemorySize, GEMM_SMEM);
    cudaFuncSetAttribute(gemm_mm<2>, cudaFuncAttributeMaxDynamicSharedMemorySize, GEMM_SMEM);
    cudaFuncSetAttribute(gemm_mm<3>, cudaFuncAttributeMaxDynamicSharedMemorySize, GEMM_SMEM);
    cudaFuncSetAttribute(corr_mm,    cudaFuncAttributeMaxDynamicSharedMemorySize, GEMM_SMEM);

    Ptrs p;
    cudaGetSymbolAddress((void**)&p.S,   g_S);
    cudaGetSymbolAddress((void**)&p.T,   g_T);
    cudaGetSymbolAddress((void**)&p.R,   g_R);
    cudaGetSymbolAddress((void**)&p.SW,  g_SW);
    cudaGetSymbolAddress((void**)&p.IDX, g_IDX);
    cudaGetSymbolAddress((void**)&p.hXS, g_hXS);
    cudaGetSymbolAddress((void**)&p.hXW, g_hXW);
    cudaGetSymbolAddress((void**)&p.hQ,  g_hQ);
    cudaGetSymbolAddress((void**)&p.hK,  g_hK);
    cudaGetSymbolAddress((void**)&p.hV,  g_hV);
    cudaGetSymbolAddress((void**)&p.hS,  g_hS);
    cudaGetSymbolAddress((void**)&p.hO,  g_hO);
    cudaGetSymbolAddress((void**)&p.hW1, g_hW1);
    cudaGetSymbolAddress((void**)&p.hT,  g_hT);
    cudaGetSymbolAddress((void**)&p.hH,  g_hH);
    cudaGetSymbolAddress((void**)&p.hW,  g_hW);
    cudaGetSymbolAddress((void**)&p.hWT, g_hWT);

    // input conversions (only standalone big cvts)
    cvt_h(x_s, p.hXS, BLD);
    cvt_h(x_w, p.hXW, BLD);

    // 1) wc_decomp1: q=x_w, k=v=x_s;  S = x_s + attn;  dual (S f32, hS half)
    run_attn(p.hXW, p.hXS, wc1_W, wc1_b, x_s, p.S, p.hS, p);

    // 2) W1 = token_embed(x_w, wc1_proj) -> half only (plain fp16, 3 shifted passes)
    wtrans_h_kernel<<<3*DD*DD/256, 256>>>(wc1_proj, p.hWT);
    launch_gemm(1, p.hXW, p.hWT, nullptr, p.hW1, nullptr, nullptr, nullptr, nullptr,
                DD, DD, 3, 0);

    // 3) self-attention: T = S + attn(S,S,S)  (f32 only; feeds movavg)
    run_attn(p.hS, p.hS, attn_W, attn_b, p.S, p.T, nullptr, p);

    // 4) S = series_decomp(T), dual-store (S f32 + hS half)
    movavg_kernel<<<dim3(16, BB), 128>>>(p.T, p.S, p.hS);

    // 5) wc_decomp2: q=W1, k=v=S;  T = S + attn;  dual (T f32, hT half)
    run_attn(p.hW1, p.hS, wc2_W, wc2_b, p.S, p.T, p.hT, p);

    // 6) x_w_new = token_embed(W1, wc2_proj) -> f32 output (plain fp16, 3 passes)
    wtrans_h_kernel<<<3*DD*DD/256, 256>>>(wc2_proj, p.hWT);
    launch_gemm(0, p.hW1, p.hWT, out_w, nullptr, nullptr, nullptr, nullptr, nullptr,
                DD, DD, 3, 0);

    // 7) FFN: hH = relu(hT @ conv1^T); S = T + hH @ conv2^T
    cvt_h(conv1_W, p.hW, (size_t)DFF*DD);
    launch_gemm(1, p.hT, p.hW, nullptr, p.hH, nullptr, nullptr, nullptr, nullptr,
                DFF, DD, 1, 1);
    cvt_h(conv2_W, p.hW, (size_t)DD*DFF);
    launch_gemm(0, p.hH, p.hW, p.S, nullptr, nullptr, nullptr, nullptr, p.T,
                DD, DFF, 1, 0);

    // 8) res = series_decomp(S) -> first output (f32 only)
    movavg_kernel<<<dim3(16, BB), 128>>>(p.S, out_res, nullptr);
}

// round 14
// speedup vs baseline: 6.3153x; 1.0425x over previous
#include <cuda_runtime.h>
#include <cuda_fp16.h>
#include <cstdint>
#include <cstddef>

#define BB  16
#define LL  1536
#define DD  512
#define DFF 2048
#define BLD (BB*LL*DD)
#define M_TOTAL (BB*LL)

// tiles: 128x128 CTA, BK = 64 halves (128 bytes/row), 8 warps of 64x32
#define BM 128
#define BN 128
#define A_TILE 16384
#define STAGE_BYTES (2*A_TILE)
#define NSTAGE 3
#define GEMM_SMEM (NSTAGE*STAGE_BYTES)  // 98304

// ---------------- device scratch ----------------
__device__ float  g_S[BLD];
__device__ float  g_T[BLD];
__device__ float  g_R[BB*LL];
__device__ float  g_SW[BB*8];
__device__ int    g_IDX[8];
__device__ __half g_hXS[BLD];
__device__ __half g_hXW[BLD];
__device__ __half g_hQ[BLD];
__device__ __half g_hK[BLD];
__device__ __half g_hV[BLD];
__device__ __half g_hS[BLD];
__device__ __half g_hO[BLD];
__device__ __half g_hW1[BLD];
__device__ __half g_hT[BLD];
__device__ __half g_hH[(size_t)BB*LL*DFF];
__device__ __half g_hWa[4*DD*DD];
__device__ __half g_hWb[4*DD*DD];
__device__ __half g_hWc[4*DD*DD];
__device__ __half g_hWT1[3*DD*DD];
__device__ __half g_hWT2[3*DD*DD];
__device__ __half g_hC1[(size_t)DFF*DD];
__device__ __half g_hC2[(size_t)DD*DFF];

// ---------------- static stream/event resources (created at program load,
// long before the harness's correctness run or graph capture) ----------------
struct CudaRes {
    cudaStream_t s1, s2;
    cudaEvent_t evRoot, evXW, evPrep, evW1, evEmb;
    CudaRes() {
        cudaStreamCreateWithFlags(&s1, cudaStreamNonBlocking);
        cudaStreamCreateWithFlags(&s2, cudaStreamNonBlocking);
        cudaEventCreateWithFlags(&evRoot, cudaEventDisableTiming);
        cudaEventCreateWithFlags(&evXW,   cudaEventDisableTiming);
        cudaEventCreateWithFlags(&evPrep, cudaEventDisableTiming);
        cudaEventCreateWithFlags(&evW1,   cudaEventDisableTiming);
        cudaEventCreateWithFlags(&evEmb,  cudaEventDisableTiming);
    }
};
static CudaRes g_res;

// ---------------- PTX helpers ----------------
__device__ __forceinline__ uint32_t smem_u32(const void* p) {
    uint32_t a;
    asm("{ .reg .u64 t; cvta.to.shared.u64 t, %1; cvt.u32.u64 %0, t; }" : "=r"(a) : "l"(p));
    return a;
}
__device__ __forceinline__ void cp16(uint32_t s, const void* g) {
    asm volatile("cp.async.cg.shared.global [%0], [%1], 16;" :: "r"(s), "l"(g));
}
__device__ __forceinline__ void cp_commit() {
    asm volatile("cp.async.commit_group;" ::: "memory");
}
template<int N> __device__ __forceinline__ void cp_wait() {
    asm volatile("cp.async.wait_group %0;" :: "n"(N) : "memory");
}
__device__ __forceinline__ void mma_f16(float* d, const uint32_t* a, const uint32_t* b) {
    asm volatile("mma.sync.aligned.m16n8k16.row.col.f32.f16.f16.f32 "
        "{%0,%1,%2,%3}, {%4,%5,%6,%7}, {%8,%9}, {%0,%1,%2,%3};"
        : "+f"(d[0]), "+f"(d[1]), "+f"(d[2]), "+f"(d[3])
        : "r"(a[0]), "r"(a[1]), "r"(a[2]), "r"(a[3]), "r"(b[0]), "r"(b[1]));
}
__device__ __forceinline__ void ldsm4(uint32_t& r0, uint32_t& r1, uint32_t& r2, uint32_t& r3,
                                      uint32_t a) {
    asm volatile("ldmatrix.sync.aligned.m8n8.x4.shared.b16 {%0,%1,%2,%3}, [%4];"
        : "=r"(r0), "=r"(r1), "=r"(r2), "=r"(r3) : "r"(a));
}
__device__ __forceinline__ uint32_t swz16(uint32_t o) { return o ^ ((o >> 3) & 0x70); }

// =====================================================================
// fp16 HMMA GEMM: C = sum_pass A_pass[M,K] @ B_pass[N,K]^T (+bias)(+resid f32)(relu)
// MODE 0: f32 out.  MODE 1: half out.  MODE 2: dual f32+half.  MODE 3: split half dsts.
// npasses>1: embed conv; pass p shifts A rows circularly by (p-1) within each LL batch.
// =====================================================================
template<int MODE>
__global__ __launch_bounds__(256, 2)
void gemm_mm(const __half* __restrict__ A, const __half* __restrict__ B,
             float* __restrict__ Cf, __half* __restrict__ Ch0,
             __half* __restrict__ Ch1, __half* __restrict__ Ch2,
             const float* __restrict__ bias, const float* __restrict__ resid,
             int N, int K, int npasses, int relu)
{
    extern __shared__ char smem[];
    const uint32_t sb = smem_u32(smem);
    const int tid = threadIdx.x;
    const int lane = tid & 31, wid = tid >> 5;
    const int wr = wid & 1, wc = wid >> 1;
    const int m0 = blockIdx.y * BM, n0 = blockIdx.x * BN;
    const int kSteps = K / 64;
    const int T = npasses * kSteps;

    int arow[4], achk[4];
#pragma unroll
    for (int u = 0; u < 4; u++) { int q = tid*4 + u; arow[u] = q >> 3; achk[u] = q & 7; }

    auto load_stage = [&](int t) {
        int pass = (npasses > 1) ? (t / kSteps) : 0;
        int k0 = (t - pass * kSteps) * 64;
        uint32_t sA = sb + (t % NSTAGE) * STAGE_BYTES;
        uint32_t sB = sA + A_TILE;
        const __half* Bp = B + (size_t)pass * N * K;
#pragma unroll
        for (int u = 0; u < 4; u++) {
            int m = m0 + arow[u], rg = m;
            if (npasses > 1) {
                int b = m / LL, l = m - b * LL;
                l += pass - 1;
                if (l < 0) l += LL; else if (l >= LL) l -= LL;
                rg = b * LL + l;
            }
            cp16(sA + swz16(arow[u]*128 + achk[u]*16),
                 A + (size_t)rg * K + k0 + achk[u]*8);
        }
#pragma unroll
        for (int u = 0; u < 4; u++)
            cp16(sB + swz16(arow[u]*128 + achk[u]*16),
                 Bp + (size_t)(n0 + arow[u]) * K + k0 + achk[u]*8);
        cp_commit();
    };

    load_stage(0); load_stage(1);

    float acc[4][4][4];
#pragma unroll
    for (int i = 0; i < 4; i++)
#pragma unroll
        for (int j = 0; j < 4; j++)
#pragma unroll
            for (int r = 0; r < 4; r++) acc[i][j][r] = 0.f;

    const int sw = lane & 7;
    int aoffs[4], boffs[2];
#pragma unroll
    for (int i = 0; i < 4; i++)
        aoffs[i] = (wr*64 + i*16 + ((lane >> 3) & 1)*8 + sw) * 128;
#pragma unroll
    for (int jp = 0; jp < 2; jp++)
        boffs[jp] = (wc*32 + jp*16 + ((lane >> 4) & 1)*8 + sw) * 128;
    const int aC = lane >> 4;
    const int bC = (lane >> 3) & 1;

    for (int t = 0; t < T; t++) {
        int rem = T - 1 - t;
        if (rem >= 1) cp_wait<1>(); else cp_wait<0>();
        __syncthreads();
        if (t + 2 < T) load_stage(t + 2);

        uint32_t sA = sb + (t % NSTAGE) * STAGE_BYTES;
        uint32_t sB = sA + A_TILE;
#pragma unroll
        for (int s16 = 0; s16 < 4; s16++) {
            uint32_t af[4][4], bf[4][2];
            uint32_t ach = (uint32_t)(((s16*2 + aC) ^ sw) << 4);
            uint32_t bch = (uint32_t)(((s16*2 + bC) ^ sw) << 4);
#pragma unroll
            for (int i = 0; i < 4; i++)
                ldsm4(af[i][0], af[i][1], af[i][2], af[i][3], sA + aoffs[i] + ach);
#pragma unroll
            for (int jp = 0; jp < 2; jp++)
                ldsm4(bf[2*jp][0], bf[2*jp][1], bf[2*jp+1][0], bf[2*jp+1][1],
                      sB + boffs[jp] + bch);
#pragma unroll
            for (int i = 0; i < 4; i++)
#pragma unroll
                for (int j = 0; j < 4; j++)
                    mma_f16(acc[i][j], af[i], bf[j]);
        }
    }

    // epilogue
#pragma unroll
    for (int i = 0; i < 4; i++) {
        int mrow = m0 + wr*64 + i*16 + (lane >> 2);
#pragma unroll
        for (int j = 0; j < 4; j++) {
            int n = n0 + wc*32 + j*8 + 2*(lane & 3);
#pragma unroll
            for (int h = 0; h < 2; h++) {
                int mm = mrow + h*8;
                float vx = acc[i][j][2*h+0], vy = acc[i][j][2*h+1];
                if (bias)  { vx += bias[n]; vy += bias[n+1]; }
                if (resid) {
                    float2 rv = *reinterpret_cast<const float2*>(&resid[(size_t)mm*N + n]);
                    vx += rv.x; vy += rv.y;
                }
                if (relu) { vx = fmaxf(vx, 0.f); vy = fmaxf(vy, 0.f); }
                if (MODE == 0 || MODE == 2) {
                    float2 v; v.x = vx; v.y = vy;
                    *reinterpret_cast<float2*>(&Cf[(size_t)mm*N + n]) = v;
                }
                if (MODE == 1 || MODE == 2) {
                    __half2 hv = __floats2half2_rn(vx, vy);
                    *reinterpret_cast<__half2*>(&Ch0[(size_t)mm*N + n]) = hv;
                }
                if (MODE == 3) {
                    __half* dst = (n < 512) ? Ch0 : ((n < 1024) ? Ch1 : Ch2);
                    int col = n & 511;
                    __half2 hv = __floats2half2_rn(vx, vy);
                    *reinterpret_cast<__half2*>(&dst[(size_t)mm*512 + col]) = hv;
                }
            }
        }
    }
}

// =====================================================================
// corr: r[b,tau] += diagonal sums of Q_b K_b^T over 128x128 tiles (fp16)
// =====================================================================
__global__ __launch_bounds__(256, 2)
void corr_mm(const __half* __restrict__ Q, const __half* __restrict__ Kb,
             float* __restrict__ r)
{
    extern __shared__ char smem[];
    const uint32_t sb = smem_u32(smem);
    const int tid = threadIdx.x;
    const int lane = tid & 31, wid = tid >> 5;
    const int wr = wid & 1, wc = wid >> 1;
    const int b = blockIdx.z;
    const int i0 = blockIdx.y * BM, j0 = blockIdx.x * BN;
    const __half* Qb = Q + (size_t)b * LL * DD;
    const __half* KB = Kb + (size_t)b * LL * DD;
    const int T = DD / 64;   // 8

    int arow[4], achk[4];
#pragma unroll
    for (int u = 0; u < 4; u++) { int q = tid*4 + u; arow[u] = q >> 3; achk[u] = q & 7; }

    auto load_stage = [&](int t) {
        int k0 = t * 64;
        uint32_t sA = sb + (t % NSTAGE) * STAGE_BYTES;
        uint32_t sB = sA + A_TILE;
#pragma unroll
        for (int u = 0; u < 4; u++)
            cp16(sA + swz16(arow[u]*128 + achk[u]*16),
                 Qb + (size_t)(i0 + arow[u]) * DD + k0 + achk[u]*8);
#pragma unroll
        for (int u = 0; u < 4; u++)
            cp16(sB + swz16(arow[u]*128 + achk[u]*16),
                 KB + (size_t)(j0 + arow[u]) * DD + k0 + achk[u]*8);
        cp_commit();
    };

    load_stage(0); load_stage(1);

    float acc[4][4][4];
#pragma unroll
    for (int i = 0; i < 4; i++)
#pragma unroll
        for (int j = 0; j < 4; j++)
#pragma unroll
            for (int q = 0; q < 4; q++) acc[i][j][q] = 0.f;

    const int sw = lane & 7;
    int aoffs[4], boffs[2];
#pragma unroll
    for (int i = 0; i < 4; i++)
        aoffs[i] = (wr*64 + i*16 + ((lane >> 3) & 1)*8 + sw) * 128;
#pragma unroll
    for (int jp = 0; jp < 2; jp++)
        boffs[jp] = (wc*32 + jp*16 + ((lane >> 4) & 1)*8 + sw) * 128;
    const int aC = lane >> 4;
    const int bC = (lane >> 3) & 1;

    for (int t = 0; t < T; t++) {
        int rem = T - 1 - t;
        if (rem >= 1) cp_wait<1>(); else cp_wait<0>();
        __syncthreads();
        if (t + 2 < T) load_stage(t + 2);

        uint32_t sA = sb + (t % NSTAGE) * STAGE_BYTES;
        uint32_t sB = sA + A_TILE;
#pragma unroll
        for (int s16 = 0; s16 < 4; s16++) {
            uint32_t af[4][4], bf[4][2];
            uint32_t ach = (uint32_t)(((s16*2 + aC) ^ sw) << 4);
            uint32_t bch = (uint32_t)(((s16*2 + bC) ^ sw) << 4);
#pragma unroll
            for (int i = 0; i < 4; i++)
                ldsm4(af[i][0], af[i][1], af[i][2], af[i][3], sA + aoffs[i] + ach);
#pragma unroll
            for (int jp = 0; jp < 2; jp++)
                ldsm4(bf[2*jp][0], bf[2*jp][1], bf[2*jp+1][0], bf[2*jp+1][1],
                      sB + boffs[jp] + bch);
#pragma unroll
            for (int i = 0; i < 4; i++)
#pragma unroll
                for (int j = 0; j < 4; j++)
                    mma_f16(acc[i][j], af[i], bf[j]);
        }
    }

    __syncthreads();
    float* Cs = (float*)smem;   // 128 x 130
#pragma unroll
    for (int i = 0; i < 4; i++) {
        int mrow = wr*64 + i*16 + (lane >> 2);
#pragma unroll
        for (int j = 0; j < 4; j++) {
            int n = wc*32 + j*8 + 2*(lane & 3);
#pragma unroll
            for (int h = 0; h < 2; h++) {
                float2 v; v.x = acc[i][j][2*h+0]; v.y = acc[i][j][2*h+1];
                *reinterpret_cast<float2*>(&Cs[(mrow + h*8)*130 + n]) = v;
            }
        }
    }
    __syncthreads();

    if (tid < 255) {
        int d = tid - 127;
        int ilo = d > 0 ? d : 0;
        int ihi = d < 0 ? 127 + d : 127;
        float s = 0.f;
        for (int i = ilo; i <= ihi; i++) s += Cs[i*130 + (i - d)];
        int tau = (i0 - j0 + d) % LL;
        if (tau < 0) tau += LL;
        atomicAdd(&r[(size_t)b * LL + tau], s);
    }
}

// ---------------- small kernels ----------------
__global__ void zero_kernel(float* p, int n)
{
    int i = blockIdx.x * 256 + threadIdx.x;
    if (i < n) p[i] = 0.f;
}

__global__ void cvt_h_kernel(const float* __restrict__ x, __half* __restrict__ y, int n4)
{
    int i = blockIdx.x * 256 + threadIdx.x;
    if (i < n4) {
        float4 v = reinterpret_cast<const float4*>(x)[i];
        reinterpret_cast<__half2*>(y)[2*i]   = __floats2half2_rn(v.x, v.y);
        reinterpret_cast<__half2*>(y)[2*i+1] = __floats2half2_rn(v.z, v.w);
    }
}

// W[n, k*3+p] (f32) -> Wt[p][n][k] (half, K-major per pass)
__global__ void wtrans_h_kernel(const float* __restrict__ Wp, __half* __restrict__ Wt)
{
    int idx = blockIdx.x * 256 + threadIdx.x;   // 3*512*512
    int p = idx / (DD*DD);
    int rr = idx - p * (DD*DD);
    int n = rr >> 9, k = rr & 511;
    Wt[idx] = __float2half_rn(Wp[n * (DD*3) + k * 3 + p]);
}

__global__ void topk_kernel(const float* __restrict__ r, int* __restrict__ gidx,
                            float* __restrict__ gsw)
{
    __shared__ float gv[LL];
    __shared__ float rv[256];
    __shared__ int   ri[256];
    __shared__ int   sidx[7];
    const int tid = threadIdx.x;

    for (int t = tid; t < LL; t += 256) {
        float s = 0.f;
        for (int b = 0; b < BB; b++) s += r[(size_t)b*LL + t];
        gv[t] = s;
    }
    __syncthreads();

    for (int it = 0; it < 7; it++) {
        float bv = -3.4e38f; int bi = 0;
        for (int t = tid; t < LL; t += 256) {
            float v = gv[t];
            if (v > bv) { bv = v; bi = t; }
        }
        rv[tid] = bv; ri[tid] = bi;
        __syncthreads();
        for (int s = 128; s > 0; s >>= 1) {
            if (tid < s) {
                if (rv[tid+s] > rv[tid] ||
                    (rv[tid+s] == rv[tid] && ri[tid+s] < ri[tid])) {
                    rv[tid] = rv[tid+s]; ri[tid] = ri[tid+s];
                }
            }
            __syncthreads();
        }
        if (tid == 0) { sidx[it] = ri[0]; gv[ri[0]] = -3.4e38f; }
        __syncthreads();
    }

    if (tid < 7) gidx[tid] = sidx[tid];
    if (tid < BB) {
        float w[7], m = -3.4e38f;
        for (int i = 0; i < 7; i++) {
            w[i] = r[(size_t)tid*LL + sidx[i]] * (1.0f / (float)DD);
            m = fmaxf(m, w[i]);
        }
        float sum = 0.f;
        for (int i = 0; i < 7; i++) { w[i] = expf(w[i] - m); sum += w[i]; }
        float inv = 1.0f / sum;
        for (int i = 0; i < 7; i++) gsw[tid*7 + i] = w[i] * inv;
    }
}

// aggregation in half: O[b,l,:] = sum_i w[b,i]*V[b,(l+idx[i])%L,:]
__global__ __launch_bounds__(256)
void agg_h_kernel(const __half* __restrict__ V, __half* __restrict__ O,
                  const int* __restrict__ idxp, const float* __restrict__ swp)
{
    int g = blockIdx.x * 256 + threadIdx.x;     // over BLD/8
    int d8 = g & 63;
    int l  = (g >> 6) % LL;
    int b  = g / (LL * 64);

    int   idx[7];
    float w[7];
#pragma unroll
    for (int i = 0; i < 7; i++) { idx[i] = idxp[i]; w[i] = swp[b*7 + i]; }

    const uint4* Vb = reinterpret_cast<const uint4*>(V + (size_t)b * LL * DD);
    float acc[8];
#pragma unroll
    for (int q = 0; q < 8; q++) acc[q] = 0.f;
#pragma unroll
    for (int i = 0; i < 7; i++) {
        int ls = l + idx[i];
        if (ls >= LL) ls -= LL;
        uint4 v = Vb[(size_t)ls * 64 + d8];
        const __half2* hp = reinterpret_cast<const __half2*>(&v);
#pragma unroll
        for (int q = 0; q < 4; q++) {
            float2 f = __half22float2(hp[q]);
            acc[2*q+0] += w[i] * f.x;
            acc[2*q+1] += w[i] * f.y;
        }
    }
    uint4 out;
    __half2* op = reinterpret_cast<__half2*>(&out);
#pragma unroll
    for (int q = 0; q < 4; q++) op[q] = __floats2half2_rn(acc[2*q], acc[2*q+1]);
    reinterpret_cast<uint4*>(O)[g] = out;
}

// series_decomp with optional half mirror output
__global__ __launch_bounds__(128)
void movavg_kernel(const float* __restrict__ X, float* __restrict__ out,
                   __half* __restrict__ outh)
{
    const int b  = blockIdx.y;
    const int l0 = blockIdx.x * 96;
    const int d4 = threadIdx.x;
    const float4* x = reinterpret_cast<const float4*>(X + (size_t)b * LL * DD) + d4;
    float4* o = reinterpret_cast<float4*>(out + (size_t)b * LL * DD) + d4;
    __half2* oh = outh ? (reinterpret_cast<__half2*>(outh + (size_t)b * LL * DD) + d4*2)
                       : (__half2*)nullptr;

    float4 s = {0.f, 0.f, 0.f, 0.f};
    for (int j = -12; j <= 12; j++) {
        int lc = l0 + j;
        if (lc < 0) lc = 0;
        if (lc > LL-1) lc = LL-1;
        float4 v = x[(size_t)lc * 128];
        s.x += v.x; s.y += v.y; s.z += v.z; s.w += v.w;
    }
    const float inv = 1.0f / 25.0f;
    for (int t = 0; t < 96; t++) {
        int l = l0 + t;
        float4 xc = x[(size_t)l * 128];
        float4 rr;
        rr.x = xc.x - s.x * inv; rr.y = xc.y - s.y * inv;
        rr.z = xc.z - s.z * inv; rr.w = xc.w - s.w * inv;
        o[(size_t)l * 128] = rr;
        if (outh) {
            oh[(size_t)l * 256]     = __floats2half2_rn(rr.x, rr.y);
            oh[(size_t)l * 256 + 1] = __floats2half2_rn(rr.z, rr.w);
        }
        int la = l + 13; if (la > LL-1) la = LL-1;
        int lr = l - 12; if (lr < 0)    lr = 0;
        float4 va = x[(size_t)la * 128];
        float4 vr = x[(size_t)lr * 128];
        s.x += va.x - vr.x; s.y += va.y - vr.y;
        s.z += va.z - vr.z; s.w += va.w - vr.w;
    }
}

// ---------------- host orchestration ----------------
static void cvt_h(const float* x, __half* y, size_t n, cudaStream_t st)
{
    cvt_h_kernel<<<(int)((n/4 + 255)/256), 256, 0, st>>>(x, y, (int)(n/4));
}

static void launch_gemm(int mode, const __half* A, const __half* B,
                        float* Cf, __half* h0, __half* h1, __half* h2,
                        const float* bias, const float* resid,
                        int N, int K, int npasses, int relu, cudaStream_t st)
{
    dim3 grid(N / BN, M_TOTAL / BM);
    switch (mode) {
    case 0: gemm_mm<0><<<grid, 256, GEMM_SMEM, st>>>(A,B,Cf,h0,h1,h2,bias,resid,N,K,npasses,relu); break;
    case 1: gemm_mm<1><<<grid, 256, GEMM_SMEM, st>>>(A,B,Cf,h0,h1,h2,bias,resid,N,K,npasses,relu); break;
    case 2: gemm_mm<2><<<grid, 256, GEMM_SMEM, st>>>(A,B,Cf,h0,h1,h2,bias,resid,N,K,npasses,relu); break;
    default: gemm_mm<3><<<grid, 256, GEMM_SMEM, st>>>(A,B,Cf,h0,h1,h2,bias,resid,N,K,npasses,relu); break;
    }
}

struct Ptrs {
    float *S, *T, *R, *SW;
    int* IDX;
    __half *hXS, *hXW, *hQ, *hK, *hV, *hS, *hO, *hW1, *hT, *hH;
    __half *hWa, *hWb, *hWc, *hWT1, *hWT2, *hC1, *hC2;
};

// attention block on stream 0 (weights pre-converted in hW)
static void run_attn(const __half* hq, const __half* hkv,
                     const __half* hW, const float* bias,
                     const float* resid, float* Cf, __half* Ch, const Ptrs& p)
{
    if (hq == hkv) {
        launch_gemm(3, hq, hW, nullptr, p.hQ, p.hK, p.hV, bias, nullptr, 3*DD, DD, 1, 0, 0);
    } else {
        launch_gemm(1, hq,  hW, nullptr, p.hQ, nullptr, nullptr, bias, nullptr, DD, DD, 1, 0, 0);
        launch_gemm(3, hkv, hW + DD*DD, nullptr, p.hK, p.hV, nullptr, bias + DD, nullptr,
                    2*DD, DD, 1, 0, 0);
    }
    zero_kernel<<<(BB*LL + 255)/256, 256>>>(p.R, BB*LL);
    dim3 cg(LL/BN, LL/BM, BB);
    corr_mm<<<cg, 256, GEMM_SMEM>>>(p.hQ, p.hK, p.R);
    topk_kernel<<<1, 256>>>(p.R, p.IDX, p.SW);
    agg_h_kernel<<<BLD/8/256, 256>>>(p.hV, p.hO, p.IDX, p.SW);
    launch_gemm(Ch ? 2 : 0, p.hO, hW + 3*DD*DD, Cf, Ch, nullptr, nullptr,
                bias + 3*DD, resid, DD, DD, 1, 0, 0);
}

extern "C" void kernel_launch(void* const* d_in, const int* in_sizes, int n_in,
                              void* d_out, int out_size)
{
    const float* x_s      = (const float*)d_in[0];
    const float* x_w      = (const float*)d_in[1];
    const float* wc1_W    = (const float*)d_in[2];
    const float* wc1_b    = (const float*)d_in[3];
    const float* wc2_W    = (const float*)d_in[4];
    const float* wc2_b    = (const float*)d_in[5];
    const float* attn_W   = (const float*)d_in[6];
    const float* attn_b   = (const float*)d_in[7];
    const float* wc1_proj = (const float*)d_in[8];
    const float* wc2_proj = (const float*)d_in[9];
    const float* conv1_W  = (const float*)d_in[10];
    const float* conv2_W  = (const float*)d_in[11];

    float* out_res = (float*)d_out;
    float* out_w   = out_res + BLD;

    cudaFuncSetAttribute(gemm_mm<0>, cudaFuncAttributeMaxDynamicSharedMemorySize, GEMM_SMEM);
    cudaFuncSetAttribute(gemm_mm<1>, cudaFuncAttributeMaxDynamicSharedMemorySize, GEMM_SMEM);
    cudaFuncSetAttribute(gemm_mm<2>, cudaFuncAttributeMaxDynamicSharedMemorySize, GEMM_SMEM);
    cudaFuncSetAttribute(gemm_mm<3>, cudaFuncAttributeMaxDynamicSharedMemorySize, GEMM_SMEM);
    cudaFuncSetAttribute(corr_mm,    cudaFuncAttributeMaxDynamicSharedMemorySize, GEMM_SMEM);

    Ptrs p;
    cudaGetSymbolAddress((void**)&p.S,    g_S);
    cudaGetSymbolAddress((void**)&p.T,    g_T);
    cudaGetSymbolAddress((void**)&p.R,    g_R);
    cudaGetSymbolAddress((void**)&p.SW,   g_SW);
    cudaGetSymbolAddress((void**)&p.IDX,  g_IDX);
    cudaGetSymbolAddress((void**)&p.hXS,  g_hXS);
    cudaGetSymbolAddress((void**)&p.hXW,  g_hXW);
    cudaGetSymbolAddress((void**)&p.hQ,   g_hQ);
    cudaGetSymbolAddress((void**)&p.hK,   g_hK);
    cudaGetSymbolAddress((void**)&p.hV,   g_hV);
    cudaGetSymbolAddress((void**)&p.hS,   g_hS);
    cudaGetSymbolAddress((void**)&p.hO,   g_hO);
    cudaGetSymbolAddress((void**)&p.hW1,  g_hW1);
    cudaGetSymbolAddress((void**)&p.hT,   g_hT);
    cudaGetSymbolAddress((void**)&p.hH,   g_hH);
    cudaGetSymbolAddress((void**)&p.hWa,  g_hWa);
    cudaGetSymbolAddress((void**)&p.hWb,  g_hWb);
    cudaGetSymbolAddress((void**)&p.hWc,  g_hWc);
    cudaGetSymbolAddress((void**)&p.hWT1, g_hWT1);
    cudaGetSymbolAddress((void**)&p.hWT2, g_hWT2);
    cudaGetSymbolAddress((void**)&p.hC1,  g_hC1);
    cudaGetSymbolAddress((void**)&p.hC2,  g_hC2);

    cudaStream_t s1 = g_res.s1, s2 = g_res.s2;

    // ---- root fork: everything on side streams descends from this event ----
    cudaEventRecord(g_res.evRoot, 0);

    // ---- s2: all weight preparation (forked from root) ----
    cudaStreamWaitEvent(s2, g_res.evRoot, 0);
    cvt_h(wc1_W, p.hWa, (size_t)4*DD*DD, s2);
    cvt_h(attn_W, p.hWb, (size_t)4*DD*DD, s2);
    cvt_h(wc2_W, p.hWc, (size_t)4*DD*DD, s2);
    wtrans_h_kernel<<<3*DD*DD/256, 256, 0, s2>>>(wc1_proj, p.hWT1);
    wtrans_h_kernel<<<3*DD*DD/256, 256, 0, s2>>>(wc2_proj, p.hWT2);
    cvt_h(conv1_W, p.hC1, (size_t)DFF*DD, s2);
    cvt_h(conv2_W, p.hC2, (size_t)DD*DFF, s2);
    cudaEventRecord(g_res.evPrep, s2);

    // ---- stream 0: input conversions ----
    cvt_h(x_w, p.hXW, BLD, 0);
    cudaEventRecord(g_res.evXW, 0);
    cvt_h(x_s, p.hXS, BLD, 0);

    // stream 0 waits for weight prep before attention chain
    cudaStreamWaitEvent(0, g_res.evPrep, 0);

    // ---- s1: both embeds, overlapped with attn1/attn2 (forked from 0 via evXW) ----
    cudaStreamWaitEvent(s1, g_res.evXW, 0);
    cudaStreamWaitEvent(s1, g_res.evPrep, 0);
    launch_gemm(1, p.hXW, p.hWT1, nullptr, p.hW1, nullptr, nullptr, nullptr, nullptr,
                DD, DD, 3, 0, s1);                         // W1 = embed(x_w)
    cudaEventRecord(g_res.evW1, s1);
    launch_gemm(0, p.hW1, p.hWT2, out_w, nullptr, nullptr, nullptr, nullptr, nullptr,
                DD, DD, 3, 0, s1);                         // out_w = embed(W1)
    cudaEventRecord(g_res.evEmb, s1);

    // ---- stream 0: attention chain ----
    // 1) wc_decomp1: q=x_w, k=v=x_s;  S = x_s + attn;  dual (S f32, hS half)
    run_attn(p.hXW, p.hXS, p.hWa, wc1_b, x_s, p.S, p.hS, p);

    // 3) self-attention: T = S + attn(S,S,S)
    run_attn(p.hS, p.hS, p.hWb, attn_b, p.S, p.T, nullptr, p);

    // 4) S = series_decomp(T), dual-store (S f32 + hS half)
    movavg_kernel<<<dim3(16, BB), 128>>>(p.T, p.S, p.hS);

    // 5) wc_decomp2: q=W1, k=v=S (needs embed1 done)
    cudaStreamWaitEvent(0, g_res.evW1, 0);
    run_attn(p.hW1, p.hS, p.hWc, wc2_b, p.S, p.T, p.hT, p);

    // 7) FFN: hH = relu(hT @ conv1^T); S = T + hH @ conv2^T
    launch_gemm(1, p.hT, p.hC1, nullptr, p.hH, nullptr, nullptr, nullptr, nullptr,
                DFF, DD, 1, 1, 0);
    launch_gemm(0, p.hH, p.hC2, p.S, nullptr, nullptr, nullptr, nullptr, p.T,
                DD, DFF, 1, 0, 0);

    // 8) res = series_decomp(S) -> first output
    movavg_kernel<<<dim3(16, BB), 128>>>(p.S, out_res, nullptr);

    // join embed stream before capture ends
    cudaStreamWaitEvent(0, g_res.evEmb, 0);
}

// round 15
// speedup vs baseline: 6.3927x; 1.0123x over previous
#include <cuda_runtime.h>
#include <cuda_fp16.h>
#include <cstdint>
#include <cstddef>

#define BB  16
#define LL  1536
#define DD  512
#define DFF 2048
#define BLD (BB*LL*DD)
#define M_TOTAL (BB*LL)

// tiles: 128x128 CTA, BK = 64 halves (128 bytes/row), 8 warps of 64x32
#define BM 128
#define BN 128
#define A_TILE 16384
#define STAGE_BYTES (2*A_TILE)
#define NSTAGE 3
#define GEMM_SMEM (NSTAGE*STAGE_BYTES)  // 98304

// ---------------- device scratch ----------------
__device__ float  g_S[BLD];
__device__ float  g_T[BLD];
__device__ float  g_R[BB*LL];
__device__ float  g_SW[BB*8];
__device__ int    g_IDX[8];
__device__ __half g_hXS[BLD];
__device__ __half g_hXW[BLD];
__device__ __half g_hQ[BLD];
__device__ __half g_hK[BLD];
__device__ __half g_hV[BLD];
__device__ __half g_hS[BLD];
__device__ __half g_hO[BLD];
__device__ __half g_hW1[BLD];
__device__ __half g_hT[BLD];
__device__ __half g_hH[(size_t)BB*LL*DFF];
__device__ __half g_hWa[4*DD*DD];
__device__ __half g_hWb[4*DD*DD];
__device__ __half g_hWc[4*DD*DD];
__device__ __half g_hWT1[3*DD*DD];
__device__ __half g_hWT2[3*DD*DD];
__device__ __half g_hC1[(size_t)DFF*DD];
__device__ __half g_hC2[(size_t)DD*DFF];

// ---------------- static stream/event resources (created at program load) ----------------
struct CudaRes {
    cudaStream_t s1, s2;
    cudaEvent_t evRoot, evXW, evPrep, evW1, evEmb, evQ1, evC2, evQ3;
    CudaRes() {
        cudaStreamCreateWithFlags(&s1, cudaStreamNonBlocking);
        cudaStreamCreateWithFlags(&s2, cudaStreamNonBlocking);
        cudaEventCreateWithFlags(&evRoot, cudaEventDisableTiming);
        cudaEventCreateWithFlags(&evXW,   cudaEventDisableTiming);
        cudaEventCreateWithFlags(&evPrep, cudaEventDisableTiming);
        cudaEventCreateWithFlags(&evW1,   cudaEventDisableTiming);
        cudaEventCreateWithFlags(&evEmb,  cudaEventDisableTiming);
        cudaEventCreateWithFlags(&evQ1,   cudaEventDisableTiming);
        cudaEventCreateWithFlags(&evC2,   cudaEventDisableTiming);
        cudaEventCreateWithFlags(&evQ3,   cudaEventDisableTiming);
    }
};
static CudaRes g_res;

// ---------------- PTX helpers ----------------
__device__ __forceinline__ uint32_t smem_u32(const void* p) {
    uint32_t a;
    asm("{ .reg .u64 t; cvta.to.shared.u64 t, %1; cvt.u32.u64 %0, t; }" : "=r"(a) : "l"(p));
    return a;
}
__device__ __forceinline__ void cp16(uint32_t s, const void* g) {
    asm volatile("cp.async.cg.shared.global [%0], [%1], 16;" :: "r"(s), "l"(g));
}
__device__ __forceinline__ void cp_commit() {
    asm volatile("cp.async.commit_group;" ::: "memory");
}
template<int N> __device__ __forceinline__ void cp_wait() {
    asm volatile("cp.async.wait_group %0;" :: "n"(N) : "memory");
}
__device__ __forceinline__ void mma_f16(float* d, const uint32_t* a, const uint32_t* b) {
    asm volatile("mma.sync.aligned.m16n8k16.row.col.f32.f16.f16.f32 "
        "{%0,%1,%2,%3}, {%4,%5,%6,%7}, {%8,%9}, {%0,%1,%2,%3};"
        : "+f"(d[0]), "+f"(d[1]), "+f"(d[2]), "+f"(d[3])
        : "r"(a[0]), "r"(a[1]), "r"(a[2]), "r"(a[3]), "r"(b[0]), "r"(b[1]));
}
__device__ __forceinline__ void ldsm4(uint32_t& r0, uint32_t& r1, uint32_t& r2, uint32_t& r3,
                                      uint32_t a) {
    asm volatile("ldmatrix.sync.aligned.m8n8.x4.shared.b16 {%0,%1,%2,%3}, [%4];"
        : "=r"(r0), "=r"(r1), "=r"(r2), "=r"(r3) : "r"(a));
}
__device__ __forceinline__ uint32_t swz16(uint32_t o) { return o ^ ((o >> 3) & 0x70); }

// =====================================================================
// fp16 HMMA GEMM (verified): C = sum_pass A_pass @ B_pass^T (+bias)(+resid f32)(relu)
// MODE 0: f32 out.  MODE 1: half out.  MODE 2: dual f32+half.  MODE 3: split half dsts.
// =====================================================================
template<int MODE>
__global__ __launch_bounds__(256, 2)
void gemm_mm(const __half* __restrict__ A, const __half* __restrict__ B,
             float* __restrict__ Cf, __half* __restrict__ Ch0,
             __half* __restrict__ Ch1, __half* __restrict__ Ch2,
             const float* __restrict__ bias, const float* __restrict__ resid,
             int N, int K, int npasses, int relu)
{
    extern __shared__ char smem[];
    const uint32_t sb = smem_u32(smem);
    const int tid = threadIdx.x;
    const int lane = tid & 31, wid = tid >> 5;
    const int wr = wid & 1, wc = wid >> 1;
    const int m0 = blockIdx.y * BM, n0 = blockIdx.x * BN;
    const int kSteps = K / 64;
    const int T = npasses * kSteps;

    int arow[4], achk[4];
#pragma unroll
    for (int u = 0; u < 4; u++) { int q = tid*4 + u; arow[u] = q >> 3; achk[u] = q & 7; }

    auto load_stage = [&](int t) {
        int pass = (npasses > 1) ? (t / kSteps) : 0;
        int k0 = (t - pass * kSteps) * 64;
        uint32_t sA = sb + (t % NSTAGE) * STAGE_BYTES;
        uint32_t sB = sA + A_TILE;
        const __half* Bp = B + (size_t)pass * N * K;
#pragma unroll
        for (int u = 0; u < 4; u++) {
            int m = m0 + arow[u], rg = m;
            if (npasses > 1) {
                int b = m / LL, l = m - b * LL;
                l += pass - 1;
                if (l < 0) l += LL; else if (l >= LL) l -= LL;
                rg = b * LL + l;
            }
            cp16(sA + swz16(arow[u]*128 + achk[u]*16),
                 A + (size_t)rg * K + k0 + achk[u]*8);
        }
#pragma unroll
        for (int u = 0; u < 4; u++)
            cp16(sB + swz16(arow[u]*128 + achk[u]*16),
                 Bp + (size_t)(n0 + arow[u]) * K + k0 + achk[u]*8);
        cp_commit();
    };

    load_stage(0); load_stage(1);

    float acc[4][4][4];
#pragma unroll
    for (int i = 0; i < 4; i++)
#pragma unroll
        for (int j = 0; j < 4; j++)
#pragma unroll
            for (int r = 0; r < 4; r++) acc[i][j][r] = 0.f;

    const int sw = lane & 7;
    int aoffs[4], boffs[2];
#pragma unroll
    for (int i = 0; i < 4; i++)
        aoffs[i] = (wr*64 + i*16 + ((lane >> 3) & 1)*8 + sw) * 128;
#pragma unroll
    for (int jp = 0; jp < 2; jp++)
        boffs[jp] = (wc*32 + jp*16 + ((lane >> 4) & 1)*8 + sw) * 128;
    const int aC = lane >> 4;
    const int bC = (lane >> 3) & 1;

    for (int t = 0; t < T; t++) {
        int rem = T - 1 - t;
        if (rem >= 1) cp_wait<1>(); else cp_wait<0>();
        __syncthreads();
        if (t + 2 < T) load_stage(t + 2);

        uint32_t sA = sb + (t % NSTAGE) * STAGE_BYTES;
        uint32_t sB = sA + A_TILE;
#pragma unroll
        for (int s16 = 0; s16 < 4; s16++) {
            uint32_t af[4][4], bf[4][2];
            uint32_t ach = (uint32_t)(((s16*2 + aC) ^ sw) << 4);
            uint32_t bch = (uint32_t)(((s16*2 + bC) ^ sw) << 4);
#pragma unroll
            for (int i = 0; i < 4; i++)
                ldsm4(af[i][0], af[i][1], af[i][2], af[i][3], sA + aoffs[i] + ach);
#pragma unroll
            for (int jp = 0; jp < 2; jp++)
                ldsm4(bf[2*jp][0], bf[2*jp][1], bf[2*jp+1][0], bf[2*jp+1][1],
                      sB + boffs[jp] + bch);
#pragma unroll
            for (int i = 0; i < 4; i++)
#pragma unroll
                for (int j = 0; j < 4; j++)
                    mma_f16(acc[i][j], af[i], bf[j]);
        }
    }

    // epilogue
#pragma unroll
    for (int i = 0; i < 4; i++) {
        int mrow = m0 + wr*64 + i*16 + (lane >> 2);
#pragma unroll
        for (int j = 0; j < 4; j++) {
            int n = n0 + wc*32 + j*8 + 2*(lane & 3);
#pragma unroll
            for (int h = 0; h < 2; h++) {
                int mm = mrow + h*8;
                float vx = acc[i][j][2*h+0], vy = acc[i][j][2*h+1];
                if (bias)  { vx += bias[n]; vy += bias[n+1]; }
                if (resid) {
                    float2 rv = *reinterpret_cast<const float2*>(&resid[(size_t)mm*N + n]);
                    vx += rv.x; vy += rv.y;
                }
                if (relu) { vx = fmaxf(vx, 0.f); vy = fmaxf(vy, 0.f); }
                if (MODE == 0 || MODE == 2) {
                    float2 v; v.x = vx; v.y = vy;
                    *reinterpret_cast<float2*>(&Cf[(size_t)mm*N + n]) = v;
                }
                if (MODE == 1 || MODE == 2) {
                    __half2 hv = __floats2half2_rn(vx, vy);
                    *reinterpret_cast<__half2*>(&Ch0[(size_t)mm*N + n]) = hv;
                }
                if (MODE == 3) {
                    __half* dst = (n < 512) ? Ch0 : ((n < 1024) ? Ch1 : Ch2);
                    int col = n & 511;
                    __half2 hv = __floats2half2_rn(vx, vy);
                    *reinterpret_cast<__half2*>(&dst[(size_t)mm*512 + col]) = hv;
                }
            }
        }
    }
}

// =====================================================================
// corr: r[b,tau] += diagonal sums of Q_b K_b^T over 128x128 tiles (fp16)
// =====================================================================
__global__ __launch_bounds__(256, 2)
void corr_mm(const __half* __restrict__ Q, const __half* __restrict__ Kb,
             float* __restrict__ r)
{
    extern __shared__ char smem[];
    const uint32_t sb = smem_u32(smem);
    const int tid = threadIdx.x;
    const int lane = tid & 31, wid = tid >> 5;
    const int wr = wid & 1, wc = wid >> 1;
    const int b = blockIdx.z;
    const int i0 = blockIdx.y * BM, j0 = blockIdx.x * BN;
    const __half* Qb = Q + (size_t)b * LL * DD;
    const __half* KB = Kb + (size_t)b * LL * DD;
    const int T = DD / 64;   // 8

    int arow[4], achk[4];
#pragma unroll
    for (int u = 0; u < 4; u++) { int q = tid*4 + u; arow[u] = q >> 3; achk[u] = q & 7; }

    auto load_stage = [&](int t) {
        int k0 = t * 64;
        uint32_t sA = sb + (t % NSTAGE) * STAGE_BYTES;
        uint32_t sB = sA + A_TILE;
#pragma unroll
        for (int u = 0; u < 4; u++)
            cp16(sA + swz16(arow[u]*128 + achk[u]*16),
                 Qb + (size_t)(i0 + arow[u]) * DD + k0 + achk[u]*8);
#pragma unroll
        for (int u = 0; u < 4; u++)
            cp16(sB + swz16(arow[u]*128 + achk[u]*16),
                 KB + (size_t)(j0 + arow[u]) * DD + k0 + achk[u]*8);
        cp_commit();
    };

    load_stage(0); load_stage(1);

    float acc[4][4][4];
#pragma unroll
    for (int i = 0; i < 4; i++)
#pragma unroll
        for (int j = 0; j < 4; j++)
#pragma unroll
            for (int q = 0; q < 4; q++) acc[i][j][q] = 0.f;

    const int sw = lane & 7;
    int aoffs[4], boffs[2];
#pragma unroll
    for (int i = 0; i < 4; i++)
        aoffs[i] = (wr*64 + i*16 + ((lane >> 3) & 1)*8 + sw) * 128;
#pragma unroll
    for (int jp = 0; jp < 2; jp++)
        boffs[jp] = (wc*32 + jp*16 + ((lane >> 4) & 1)*8 + sw) * 128;
    const int aC = lane >> 4;
    const int bC = (lane >> 3) & 1;

    for (int t = 0; t < T; t++) {
        int rem = T - 1 - t;
        if (rem >= 1) cp_wait<1>(); else cp_wait<0>();
        __syncthreads();
        if (t + 2 < T) load_stage(t + 2);

        uint32_t sA = sb + (t % NSTAGE) * STAGE_BYTES;
        uint32_t sB = sA + A_TILE;
#pragma unroll
        for (int s16 = 0; s16 < 4; s16++) {
            uint32_t af[4][4], bf[4][2];
            uint32_t ach = (uint32_t)(((s16*2 + aC) ^ sw) << 4);
            uint32_t bch = (uint32_t)(((s16*2 + bC) ^ sw) << 4);
#pragma unroll
            for (int i = 0; i < 4; i++)
                ldsm4(af[i][0], af[i][1], af[i][2], af[i][3], sA + aoffs[i] + ach);
#pragma unroll
            for (int jp = 0; jp < 2; jp++)
                ldsm4(bf[2*jp][0], bf[2*jp][1], bf[2*jp+1][0], bf[2*jp+1][1],
                      sB + boffs[jp] + bch);
#pragma unroll
            for (int i = 0; i < 4; i++)
#pragma unroll
                for (int j = 0; j < 4; j++)
                    mma_f16(acc[i][j], af[i], bf[j]);
        }
    }

    __syncthreads();
    float* Cs = (float*)smem;   // 128 x 130
#pragma unroll
    for (int i = 0; i < 4; i++) {
        int mrow = wr*64 + i*16 + (lane >> 2);
#pragma unroll
        for (int j = 0; j < 4; j++) {
            int n = wc*32 + j*8 + 2*(lane & 3);
#pragma unroll
            for (int h = 0; h < 2; h++) {
                float2 v; v.x = acc[i][j][2*h+0]; v.y = acc[i][j][2*h+1];
                *reinterpret_cast<float2*>(&Cs[(mrow + h*8)*130 + n]) = v;
            }
        }
    }
    __syncthreads();

    if (tid < 255) {
        int d = tid - 127;
        int ilo = d > 0 ? d : 0;
        int ihi = d < 0 ? 127 + d : 127;
        float s = 0.f;
        for (int i = ilo; i <= ihi; i++) s += Cs[i*130 + (i - d)];
        int tau = (i0 - j0 + d) % LL;
        if (tau < 0) tau += LL;
        atomicAdd(&r[(size_t)b * LL + tau], s);
    }
}

// ---------------- fused prep: all weight conversions + R zero in ONE kernel ----------------
// work items: [0,262144)x5 vec4-cvt regions, then 2x786432 scalar wtrans, then 6144 vec4 zero
__global__ void prep_all_kernel(
    const float* __restrict__ wc1_W, const float* __restrict__ attn_W,
    const float* __restrict__ wc2_W, const float* __restrict__ conv1_W,
    const float* __restrict__ conv2_W, const float* __restrict__ wc1_proj,
    const float* __restrict__ wc2_proj,
    __half* __restrict__ hWa, __half* __restrict__ hWb, __half* __restrict__ hWc,
    __half* __restrict__ hC1, __half* __restrict__ hC2,
    __half* __restrict__ hWT1, __half* __restrict__ hWT2,
    float* __restrict__ R)
{
    int gid = blockIdx.x * 256 + threadIdx.x;
    if (gid < 1310720) {
        // vec4 f32->f16 convert regions (each 262144 float4 = 1M floats)
        int rgn = gid / 262144;
        int i = gid - rgn * 262144;
        const float* src; __half* dst;
        switch (rgn) {
        case 0: src = wc1_W;  dst = hWa; break;
        case 1: src = attn_W; dst = hWb; break;
        case 2: src = wc2_W;  dst = hWc; break;
        case 3: src = conv1_W; dst = hC1; break;
        default: src = conv2_W; dst = hC2; break;
        }
        float4 v = reinterpret_cast<const float4*>(src)[i];
        reinterpret_cast<__half2*>(dst)[2*i]   = __floats2half2_rn(v.x, v.y);
        reinterpret_cast<__half2*>(dst)[2*i+1] = __floats2half2_rn(v.z, v.w);
    } else if (gid < 2883584) {
        // wtrans: W[n, k*3+p] -> Wt[p][n][k] (scalar)
        int j = gid - 1310720;
        const float* src = wc1_proj; __half* dst = hWT1;
        if (j >= 786432) { j -= 786432; src = wc2_proj; dst = hWT2; }
        int p = j / (DD*DD);
        int rr = j - p * (DD*DD);
        int n = rr >> 9, k = rr & 511;
        dst[j] = __float2half_rn(src[n * (DD*3) + k * 3 + p]);
    } else if (gid < 2889728) {
        int j = gid - 2883584;
        reinterpret_cast<float4*>(R)[j] = make_float4(0.f, 0.f, 0.f, 0.f);
    }
}

__global__ void zero_kernel(float* p, int n)
{
    int i = blockIdx.x * 256 + threadIdx.x;
    if (i < n) p[i] = 0.f;
}

__global__ void cvt_h_kernel(const float* __restrict__ x, __half* __restrict__ y, int n4)
{
    int i = blockIdx.x * 256 + threadIdx.x;
    if (i < n4) {
        float4 v = reinterpret_cast<const float4*>(x)[i];
        reinterpret_cast<__half2*>(y)[2*i]   = __floats2half2_rn(v.x, v.y);
        reinterpret_cast<__half2*>(y)[2*i+1] = __floats2half2_rn(v.z, v.w);
    }
}

__global__ void topk_kernel(const float* __restrict__ r, int* __restrict__ gidx,
                            float* __restrict__ gsw)
{
    __shared__ float gv[LL];
    __shared__ float rv[256];
    __shared__ int   ri[256];
    __shared__ int   sidx[7];
    const int tid = threadIdx.x;

    for (int t = tid; t < LL; t += 256) {
        float s = 0.f;
        for (int b = 0; b < BB; b++) s += r[(size_t)b*LL + t];
        gv[t] = s;
    }
    __syncthreads();

    for (int it = 0; it < 7; it++) {
        float bv = -3.4e38f; int bi = 0;
        for (int t = tid; t < LL; t += 256) {
            float v = gv[t];
            if (v > bv) { bv = v; bi = t; }
        }
        rv[tid] = bv; ri[tid] = bi;
        __syncthreads();
        for (int s = 128; s > 0; s >>= 1) {
            if (tid < s) {
                if (rv[tid+s] > rv[tid] ||
                    (rv[tid+s] == rv[tid] && ri[tid+s] < ri[tid])) {
                    rv[tid] = rv[tid+s]; ri[tid] = ri[tid+s];
                }
            }
            __syncthreads();
        }
        if (tid == 0) { sidx[it] = ri[0]; gv[ri[0]] = -3.4e38f; }
        __syncthreads();
    }

    if (tid < 7) gidx[tid] = sidx[tid];
    if (tid < BB) {
        float w[7], m = -3.4e38f;
        for (int i = 0; i < 7; i++) {
            w[i] = r[(size_t)tid*LL + sidx[i]] * (1.0f / (float)DD);
            m = fmaxf(m, w[i]);
        }
        float sum = 0.f;
        for (int i = 0; i < 7; i++) { w[i] = expf(w[i] - m); sum += w[i]; }
        float inv = 1.0f / sum;
        for (int i = 0; i < 7; i++) gsw[tid*7 + i] = w[i] * inv;
    }
}

__global__ __launch_bounds__(256)
void agg_h_kernel(const __half* __restrict__ V, __half* __restrict__ O,
                  const int* __restrict__ idxp, const float* __restrict__ swp)
{
    int g = blockIdx.x * 256 + threadIdx.x;
    int d8 = g & 63;
    int l  = (g >> 6) % LL;
    int b  = g / (LL * 64);

    int   idx[7];
    float w[7];
#pragma unroll
    for (int i = 0; i < 7; i++) { idx[i] = idxp[i]; w[i] = swp[b*7 + i]; }

    const uint4* Vb = reinterpret_cast<const uint4*>(V + (size_t)b * LL * DD);
    float acc[8];
#pragma unroll
    for (int q = 0; q < 8; q++) acc[q] = 0.f;
#pragma unroll
    for (int i = 0; i < 7; i++) {
        int ls = l + idx[i];
        if (ls >= LL) ls -= LL;
        uint4 v = Vb[(size_t)ls * 64 + d8];
        const __half2* hp = reinterpret_cast<const __half2*>(&v);
#pragma unroll
        for (int q = 0; q < 4; q++) {
            float2 f = __half22float2(hp[q]);
            acc[2*q+0] += w[i] * f.x;
            acc[2*q+1] += w[i] * f.y;
        }
    }
    uint4 out;
    __half2* op = reinterpret_cast<__half2*>(&out);
#pragma unroll
    for (int q = 0; q < 4; q++) op[q] = __floats2half2_rn(acc[2*q], acc[2*q+1]);
    reinterpret_cast<uint4*>(O)[g] = out;
}

__global__ __launch_bounds__(128)
void movavg_kernel(const float* __restrict__ X, float* __restrict__ out,
                   __half* __restrict__ outh)
{
    const int b  = blockIdx.y;
    const int l0 = blockIdx.x * 96;
    const int d4 = threadIdx.x;
    const float4* x = reinterpret_cast<const float4*>(X + (size_t)b * LL * DD) + d4;
    float4* o = reinterpret_cast<float4*>(out + (size_t)b * LL * DD) + d4;
    __half2* oh = outh ? (reinterpret_cast<__half2*>(outh + (size_t)b * LL * DD) + d4*2)
                       : (__half2*)nullptr;

    float4 s = {0.f, 0.f, 0.f, 0.f};
    for (int j = -12; j <= 12; j++) {
        int lc = l0 + j;
        if (lc < 0) lc = 0;
        if (lc > LL-1) lc = LL-1;
        float4 v = x[(size_t)lc * 128];
        s.x += v.x; s.y += v.y; s.z += v.z; s.w += v.w;
    }
    const float inv = 1.0f / 25.0f;
    for (int t = 0; t < 96; t++) {
        int l = l0 + t;
        float4 xc = x[(size_t)l * 128];
        float4 rr;
        rr.x = xc.x - s.x * inv; rr.y = xc.y - s.y * inv;
        rr.z = xc.z - s.z * inv; rr.w = xc.w - s.w * inv;
        o[(size_t)l * 128] = rr;
        if (outh) {
            oh[(size_t)l * 256]     = __floats2half2_rn(rr.x, rr.y);
            oh[(size_t)l * 256 + 1] = __floats2half2_rn(rr.z, rr.w);
        }
        int la = l + 13; if (la > LL-1) la = LL-1;
        int lr = l - 12; if (lr < 0)    lr = 0;
        float4 va = x[(size_t)la * 128];
        float4 vr = x[(size_t)lr * 128];
        s.x += va.x - vr.x; s.y += va.y - vr.y;
        s.z += va.z - vr.z; s.w += va.w - vr.w;
    }
}

// ---------------- host orchestration ----------------
static void cvt_h(const float* x, __half* y, size_t n, cudaStream_t st)
{
    cvt_h_kernel<<<(int)((n/4 + 255)/256), 256, 0, st>>>(x, y, (int)(n/4));
}

static void launch_gemm(int mode, const __half* A, const __half* B,
                        float* Cf, __half* h0, __half* h1, __half* h2,
                        const float* bias, const float* resid,
                        int N, int K, int npasses, int relu, cudaStream_t st)
{
    dim3 grid(N / BN, M_TOTAL / BM);
    switch (mode) {
    case 0: gemm_mm<0><<<grid, 256, GEMM_SMEM, st>>>(A,B,Cf,h0,h1,h2,bias,resid,N,K,npasses,relu); break;
    case 1: gemm_mm<1><<<grid, 256, GEMM_SMEM, st>>>(A,B,Cf,h0,h1,h2,bias,resid,N,K,npasses,relu); break;
    case 2: gemm_mm<2><<<grid, 256, GEMM_SMEM, st>>>(A,B,Cf,h0,h1,h2,bias,resid,N,K,npasses,relu); break;
    default: gemm_mm<3><<<grid, 256, GEMM_SMEM, st>>>(A,B,Cf,h0,h1,h2,bias,resid,N,K,npasses,relu); break;
    }
}

extern "C" void kernel_launch(void* const* d_in, const int* in_sizes, int n_in,
                              void* d_out, int out_size)
{
    const float* x_s      = (const float*)d_in[0];
    const float* x_w      = (const float*)d_in[1];
    const float* wc1_W    = (const float*)d_in[2];
    const float* wc1_b    = (const float*)d_in[3];
    const float* wc2_W    = (const float*)d_in[4];
    const float* wc2_b    = (const float*)d_in[5];
    const float* attn_W   = (const float*)d_in[6];
    const float* attn_b   = (const float*)d_in[7];
    const float* wc1_proj = (const float*)d_in[8];
    const float* wc2_proj = (const float*)d_in[9];
    const float* conv1_W  = (const float*)d_in[10];
    const float* conv2_W  = (const float*)d_in[11];

    float* out_res = (float*)d_out;
    float* out_w   = out_res + BLD;

    cudaFuncSetAttribute(gemm_mm<0>, cudaFuncAttributeMaxDynamicSharedMemorySize, GEMM_SMEM);
    cudaFuncSetAttribute(gemm_mm<1>, cudaFuncAttributeMaxDynamicSharedMemorySize, GEMM_SMEM);
    cudaFuncSetAttribute(gemm_mm<2>, cudaFuncAttributeMaxDynamicSharedMemorySize, GEMM_SMEM);
    cudaFuncSetAttribute(gemm_mm<3>, cudaFuncAttributeMaxDynamicSharedMemorySize, GEMM_SMEM);
    cudaFuncSetAttribute(corr_mm,    cudaFuncAttributeMaxDynamicSharedMemorySize, GEMM_SMEM);

    float *S, *T, *R, *SW; int* IDX;
    __half *hXS, *hXW, *hQ, *hK, *hV, *hS, *hO, *hW1, *hT, *hH;
    __half *hWa, *hWb, *hWc, *hWT1, *hWT2, *hC1, *hC2;
    cudaGetSymbolAddress((void**)&S,    g_S);
    cudaGetSymbolAddress((void**)&T,    g_T);
    cudaGetSymbolAddress((void**)&R,    g_R);
    cudaGetSymbolAddress((void**)&SW,   g_SW);
    cudaGetSymbolAddress((void**)&IDX,  g_IDX);
    cudaGetSymbolAddress((void**)&hXS,  g_hXS);
    cudaGetSymbolAddress((void**)&hXW,  g_hXW);
    cudaGetSymbolAddress((void**)&hQ,   g_hQ);
    cudaGetSymbolAddress((void**)&hK,   g_hK);
    cudaGetSymbolAddress((void**)&hV,   g_hV);
    cudaGetSymbolAddress((void**)&hS,   g_hS);
    cudaGetSymbolAddress((void**)&hO,   g_hO);
    cudaGetSymbolAddress((void**)&hW1,  g_hW1);
    cudaGetSymbolAddress((void**)&hT,   g_hT);
    cudaGetSymbolAddress((void**)&hH,   g_hH);
    cudaGetSymbolAddress((void**)&hWa,  g_hWa);
    cudaGetSymbolAddress((void**)&hWb,  g_hWb);
    cudaGetSymbolAddress((void**)&hWc,  g_hWc);
    cudaGetSymbolAddress((void**)&hWT1, g_hWT1);
    cudaGetSymbolAddress((void**)&hWT2, g_hWT2);
    cudaGetSymbolAddress((void**)&hC1,  g_hC1);
    cudaGetSymbolAddress((void**)&hC2,  g_hC2);

    cudaStream_t s1 = g_res.s1, s2 = g_res.s2;
    dim3 cg(LL/BN, LL/BM, BB);

    // ---- root fork ----
    cudaEventRecord(g_res.evRoot, 0);

    // [1] s2: fused weight prep (+ R zero for attn1)
    cudaStreamWaitEvent(s2, g_res.evRoot, 0);
    prep_all_kernel<<<(2889728 + 255)/256, 256, 0, s2>>>(
        wc1_W, attn_W, wc2_W, conv1_W, conv2_W, wc1_proj, wc2_proj,
        hWa, hWb, hWc, hC1, hC2, hWT1, hWT2, R);
    cudaEventRecord(g_res.evPrep, s2);

    // [2][3] stream 0: input conversions
    cvt_h(x_w, hXW, BLD, 0);
    cudaEventRecord(g_res.evXW, 0);
    cvt_h(x_s, hXS, BLD, 0);

    // [4] s2: Q1 projection (A = hXW, B = hWa) — overlaps KV1 on stream 0
    cudaStreamWaitEvent(s2, g_res.evXW, 0);
    launch_gemm(1, hXW, hWa, nullptr, hQ, nullptr, nullptr, wc1_b, nullptr,
                DD, DD, 1, 0, s2);
    cudaEventRecord(g_res.evQ1, s2);

    // stream 0 waits for weight prep
    cudaStreamWaitEvent(0, g_res.evPrep, 0);

    // [5] stream 0: KV1 (A = hXS, B = hWa+DD*DD)
    launch_gemm(3, hXS, hWa + DD*DD, nullptr, hK, hV, nullptr, wc1_b + DD, nullptr,
                2*DD, DD, 1, 0, 0);

    // [6] stream 0: corr1 (profiled by ncu -s 5)
    cudaStreamWaitEvent(0, g_res.evQ1, 0);
    corr_mm<<<cg, 256, GEMM_SMEM>>>(hQ, hK, R);

    // s1: embeds (forked; overlap with attention chain)
    cudaStreamWaitEvent(s1, g_res.evXW, 0);
    cudaStreamWaitEvent(s1, g_res.evPrep, 0);
    launch_gemm(1, hXW, hWT1, nullptr, hW1, nullptr, nullptr, nullptr, nullptr,
                DD, DD, 3, 0, s1);
    cudaEventRecord(g_res.evW1, s1);
    launch_gemm(0, hW1, hWT2, out_w, nullptr, nullptr, nullptr, nullptr, nullptr,
                DD, DD, 3, 0, s1);
    cudaEventRecord(g_res.evEmb, s1);

    // stream 0: rest of attn1
    topk_kernel<<<1, 256>>>(R, IDX, SW);
    agg_h_kernel<<<BLD/8/256, 256>>>(hV, hO, IDX, SW);
    launch_gemm(2, hO, hWa + 3*DD*DD, S, hS, nullptr, nullptr,
                wc1_b + 3*DD, x_s, DD, DD, 1, 0, 0);

    // attn2: self-attention on hS (fused QKV)
    launch_gemm(3, hS, hWb, nullptr, hQ, hK, hV, attn_b, nullptr, 3*DD, DD, 1, 0, 0);
    zero_kernel<<<(BB*LL + 255)/256, 256>>>(R, BB*LL);
    corr_mm<<<cg, 256, GEMM_SMEM>>>(hQ, hK, R);
    cudaEventRecord(g_res.evC2, 0);
    topk_kernel<<<1, 256>>>(R, IDX, SW);
    agg_h_kernel<<<BLD/8/256, 256>>>(hV, hO, IDX, SW);
    launch_gemm(0, hO, hWb + 3*DD*DD, T, nullptr, nullptr, nullptr,
                attn_b + 3*DD, S, DD, DD, 1, 0, 0);

    // series_decomp: S = decomp(T), dual store
    movavg_kernel<<<dim3(16, BB), 128>>>(T, S, hS);

    // s2: Q3 projection (A = hW1, B = hWc) — must wait corr2 done reading hQ & embed1
    cudaStreamWaitEvent(s2, g_res.evC2, 0);
    cudaStreamWaitEvent(s2, g_res.evW1, 0);
    launch_gemm(1, hW1, hWc, nullptr, hQ, nullptr, nullptr, wc2_b, nullptr,
                DD, DD, 1, 0, s2);
    cudaEventRecord(g_res.evQ3, s2);

    // stream 0: attn3 KV (A = hS), then corr3
    launch_gemm(3, hS, hWc + DD*DD, nullptr, hK, hV, nullptr, wc2_b + DD, nullptr,
                2*DD, DD, 1, 0, 0);
    zero_kernel<<<(BB*LL + 255)/256, 256>>>(R, BB*LL);
    cudaStreamWaitEvent(0, g_res.evQ3, 0);
    corr_mm<<<cg, 256, GEMM_SMEM>>>(hQ, hK, R);
    topk_kernel<<<1, 256>>>(R, IDX, SW);
    agg_h_kernel<<<BLD/8/256, 256>>>(hV, hO, IDX, SW);
    launch_gemm(2, hO, hWc + 3*DD*DD, T, hT, nullptr, nullptr,
                wc2_b + 3*DD, S, DD, DD, 1, 0, 0);

    // FFN
    launch_gemm(1, hT, hC1, nullptr, hH, nullptr, nullptr, nullptr, nullptr,
                DFF, DD, 1, 1, 0);
    launch_gemm(0, hH, hC2, S, nullptr, nullptr, nullptr, nullptr, T,
                DD, DFF, 1, 0, 0);

    // final series_decomp
    movavg_kernel<<<dim3(16, BB), 128>>>(S, out_res, nullptr);

    // join embed stream
    cudaStreamWaitEvent(0, g_res.evEmb, 0);
}